// round 1
// baseline (speedup 1.0000x reference)
#include <cuda_runtime.h>

#define H_   96
#define W_   96
#define S_   9216
#define CIN  256
#define NH   8
#define DH   32

// scratch: qkv as [g][s][d] with g = sel*8 + h (sel: 0=q,1=k,2=v)
__device__ float g_qkv[3 * NH * S_ * DH];
// attention output [s][h*32+d]
__device__ float g_attn[S_ * CIN];

// ---------------------------------------------------------------------------
// GEMM A: qkv[s][j] = sum_c x[c][s] * w_qkv[j][c] + b_qkv[j]
// x is NCHW -> [C][S] (contiguous in s). 128x128x8 tile, 8x8 per thread.
// ---------------------------------------------------------------------------
__global__ __launch_bounds__(256) void qkv_gemm(
    const float* __restrict__ x, const float* __restrict__ w,
    const float* __restrict__ bias)
{
    __shared__ float As[8][128];
    __shared__ float Bs[8][128];
    const int bm = blockIdx.x * 128;
    const int bn = blockIdx.y * 128;
    const int tid = threadIdx.x;
    const int tx = tid & 15, ty = tid >> 4;
    const int a_k = tid >> 5, a_m = (tid & 31) << 2;   // A: direct rows
    const int b_n = tid >> 1, b_k4 = (tid & 1) << 2;   // B: transpose load

    float acc[8][8];
#pragma unroll
    for (int i = 0; i < 8; i++)
#pragma unroll
        for (int j = 0; j < 8; j++) acc[i][j] = 0.f;

    for (int k0 = 0; k0 < CIN; k0 += 8) {
        float4 av = *(const float4*)&x[(k0 + a_k) * S_ + bm + a_m];
        *(float4*)&As[a_k][a_m] = av;
        float4 bv = *(const float4*)&w[(bn + b_n) * CIN + k0 + b_k4];
        Bs[b_k4 + 0][b_n] = bv.x;
        Bs[b_k4 + 1][b_n] = bv.y;
        Bs[b_k4 + 2][b_n] = bv.z;
        Bs[b_k4 + 3][b_n] = bv.w;
        __syncthreads();
#pragma unroll
        for (int kk = 0; kk < 8; kk++) {
            float4 a0 = *(float4*)&As[kk][ty * 4];
            float4 a1 = *(float4*)&As[kk][ty * 4 + 64];
            float4 b0 = *(float4*)&Bs[kk][tx * 4];
            float4 b1 = *(float4*)&Bs[kk][tx * 4 + 64];
            float am[8] = {a0.x, a0.y, a0.z, a0.w, a1.x, a1.y, a1.z, a1.w};
            float bb[8] = {b0.x, b0.y, b0.z, b0.w, b1.x, b1.y, b1.z, b1.w};
#pragma unroll
            for (int i = 0; i < 8; i++)
#pragma unroll
                for (int j = 0; j < 8; j++)
                    acc[i][j] = fmaf(am[i], bb[j], acc[i][j]);
        }
        __syncthreads();
    }

    // scatter to g_qkv[g][m][d], g = n>>5, d = n&31 (d0 4-aligned)
#pragma unroll
    for (int mi = 0; mi < 8; mi++) {
        int m = bm + ty * 4 + (mi < 4 ? mi : mi + 60);
#pragma unroll
        for (int g2 = 0; g2 < 2; g2++) {
            int n0 = bn + tx * 4 + g2 * 64;
            float4 v;
            v.x = acc[mi][g2 * 4 + 0] + bias[n0 + 0];
            v.y = acc[mi][g2 * 4 + 1] + bias[n0 + 1];
            v.z = acc[mi][g2 * 4 + 2] + bias[n0 + 2];
            v.w = acc[mi][g2 * 4 + 3] + bias[n0 + 3];
            int grp = n0 >> 5, d0 = n0 & 31;
            *(float4*)&g_qkv[(grp * S_ + m) * DH + d0] = v;
        }
    }
}

// ---------------------------------------------------------------------------
// Neighborhood attention: 16x8 query tile per block (per head).
// Key/value window 22x14 = 308 positions staged in smem (K then V, reusing
// the same buffer). smem layout: float4 [d4][pos] with PADP=309 (conflict-free).
// ---------------------------------------------------------------------------
#define TQX   16
#define TQY   8
#define WINX  22
#define WINY  14
#define NPOSW 308
#define PADP  309

__global__ __launch_bounds__(128) void natten_kernel()
{
    __shared__ float4 KVs[8 * PADP];
    const int h = blockIdx.z;
    const int qx0 = blockIdx.x * TQX, qy0 = blockIdx.y * TQY;
    const int wx0 = min(max(qx0 - 3, 0), W_ - WINX);
    const int wy0 = min(max(qy0 - 3, 0), H_ - WINY);
    const int tid = threadIdx.x;
    const int qx = qx0 + (tid & 15), qy = qy0 + (tid >> 4);
    const int s = qy * W_ + qx;

    // load q into registers
    const float* Qg = g_qkv + (h * S_ + s) * DH;
    float4 qv[8];
#pragma unroll
    for (int d4 = 0; d4 < 8; d4++) qv[d4] = *(const float4*)&Qg[d4 * 4];

    // stage K window
    const float* Kg = g_qkv + (NH + h) * S_ * DH;
    for (int i = tid; i < NPOSW * 8; i += 128) {
        int pos = i >> 3, d4 = i & 7;
        int gy = wy0 + pos / WINX, gx = wx0 + pos % WINX;
        KVs[d4 * PADP + pos] = *(const float4*)&Kg[(gy * W_ + gx) * DH + d4 * 4];
    }
    __syncthreads();

    const int by = min(max(qy, 3), H_ - 4) - 3 - wy0;
    const int bx = min(max(qx, 3), W_ - 4) - 3 - wx0;

    float sc[49];
#pragma unroll
    for (int jy = 0; jy < 7; jy++) {
#pragma unroll
        for (int jx = 0; jx < 7; jx++) {
            int pos = (by + jy) * WINX + (bx + jx);
            float4 a = make_float4(0.f, 0.f, 0.f, 0.f);
#pragma unroll
            for (int d4 = 0; d4 < 8; d4++) {
                float4 kv = KVs[d4 * PADP + pos];
                a.x = fmaf(qv[d4].x, kv.x, a.x);
                a.y = fmaf(qv[d4].y, kv.y, a.y);
                a.z = fmaf(qv[d4].z, kv.z, a.z);
                a.w = fmaf(qv[d4].w, kv.w, a.w);
            }
            sc[jy * 7 + jx] = (a.x + a.y) + (a.z + a.w);
        }
    }

    // stage V window into the same smem
    __syncthreads();
    const float* Vg = g_qkv + (2 * NH + h) * S_ * DH;
    for (int i = tid; i < NPOSW * 8; i += 128) {
        int pos = i >> 3, d4 = i & 7;
        int gy = wy0 + pos / WINX, gx = wx0 + pos % WINX;
        KVs[d4 * PADP + pos] = *(const float4*)&Vg[(gy * W_ + gx) * DH + d4 * 4];
    }
    __syncthreads();

    // softmax over 49 scores
    const float scale = 0.17677669529663687f;  // 1/sqrt(32)
    float mx = -1e30f;
#pragma unroll
    for (int j = 0; j < 49; j++) { sc[j] *= scale; mx = fmaxf(mx, sc[j]); }
    float sum = 0.f;
#pragma unroll
    for (int j = 0; j < 49; j++) { sc[j] = __expf(sc[j] - mx); sum += sc[j]; }
    float inv = 1.0f / sum;

    float4 o[8];
#pragma unroll
    for (int d4 = 0; d4 < 8; d4++) o[d4] = make_float4(0.f, 0.f, 0.f, 0.f);
#pragma unroll
    for (int jy = 0; jy < 7; jy++) {
#pragma unroll
        for (int jx = 0; jx < 7; jx++) {
            float p = sc[jy * 7 + jx] * inv;
            int pos = (by + jy) * WINX + (bx + jx);
#pragma unroll
            for (int d4 = 0; d4 < 8; d4++) {
                float4 vv = KVs[d4 * PADP + pos];
                o[d4].x = fmaf(p, vv.x, o[d4].x);
                o[d4].y = fmaf(p, vv.y, o[d4].y);
                o[d4].z = fmaf(p, vv.z, o[d4].z);
                o[d4].w = fmaf(p, vv.w, o[d4].w);
            }
        }
    }

    float* ao = g_attn + s * CIN + h * DH;
#pragma unroll
    for (int d4 = 0; d4 < 8; d4++) *(float4*)&ao[d4 * 4] = o[d4];
}

// ---------------------------------------------------------------------------
// GEMM C: out[co][s] = sum_c g_attn[s][c] * w_out[co][c] + b_out[co]
// Output written NCHW [COUT][S]. Both A and B transpose-loaded into smem.
// ---------------------------------------------------------------------------
__global__ __launch_bounds__(256) void out_gemm(
    const float* __restrict__ w, const float* __restrict__ bias,
    float* __restrict__ out)
{
    __shared__ float As[8][128];
    __shared__ float Bs[8][128];
    const int bm = blockIdx.x * 128;   // s
    const int bn = blockIdx.y * 128;   // cout
    const int tid = threadIdx.x;
    const int tx = tid & 15, ty = tid >> 4;
    const int a_m = tid >> 1, a_k4 = (tid & 1) << 2;
    const int b_n = tid >> 1, b_k4 = (tid & 1) << 2;

    float acc[8][8];
#pragma unroll
    for (int i = 0; i < 8; i++)
#pragma unroll
        for (int j = 0; j < 8; j++) acc[i][j] = 0.f;

    for (int k0 = 0; k0 < CIN; k0 += 8) {
        float4 av = *(const float4*)&g_attn[(bm + a_m) * CIN + k0 + a_k4];
        As[a_k4 + 0][a_m] = av.x;
        As[a_k4 + 1][a_m] = av.y;
        As[a_k4 + 2][a_m] = av.z;
        As[a_k4 + 3][a_m] = av.w;
        float4 bv = *(const float4*)&w[(bn + b_n) * CIN + k0 + b_k4];
        Bs[b_k4 + 0][b_n] = bv.x;
        Bs[b_k4 + 1][b_n] = bv.y;
        Bs[b_k4 + 2][b_n] = bv.z;
        Bs[b_k4 + 3][b_n] = bv.w;
        __syncthreads();
#pragma unroll
        for (int kk = 0; kk < 8; kk++) {
            float4 a0 = *(float4*)&As[kk][ty * 4];
            float4 a1 = *(float4*)&As[kk][ty * 4 + 64];
            float4 b0 = *(float4*)&Bs[kk][tx * 4];
            float4 b1 = *(float4*)&Bs[kk][tx * 4 + 64];
            float am[8] = {a0.x, a0.y, a0.z, a0.w, a1.x, a1.y, a1.z, a1.w};
            float bb[8] = {b0.x, b0.y, b0.z, b0.w, b1.x, b1.y, b1.z, b1.w};
#pragma unroll
            for (int i = 0; i < 8; i++)
#pragma unroll
                for (int j = 0; j < 8; j++)
                    acc[i][j] = fmaf(am[i], bb[j], acc[i][j]);
        }
        __syncthreads();
    }

    // epilogue: out[n][m] NCHW, float4 along m
#pragma unroll
    for (int nj = 0; nj < 8; nj++) {
        int n = bn + tx * 4 + (nj < 4 ? nj : nj + 60);
        float bo = bias[n];
        float4 v0, v1;
        v0.x = acc[0][nj] + bo; v0.y = acc[1][nj] + bo;
        v0.z = acc[2][nj] + bo; v0.w = acc[3][nj] + bo;
        v1.x = acc[4][nj] + bo; v1.y = acc[5][nj] + bo;
        v1.z = acc[6][nj] + bo; v1.w = acc[7][nj] + bo;
        *(float4*)&out[n * S_ + bm + ty * 4]      = v0;
        *(float4*)&out[n * S_ + bm + ty * 4 + 64] = v1;
    }
}

// ---------------------------------------------------------------------------
extern "C" void kernel_launch(void* const* d_in, const int* in_sizes, int n_in,
                              void* d_out, int out_size)
{
    const float* x     = (const float*)d_in[0];   // [256][9216]
    const float* w_qkv = (const float*)d_in[1];   // [768][256]
    const float* b_qkv = (const float*)d_in[2];   // [768]
    const float* w_out = (const float*)d_in[3];   // [256][256]
    const float* b_out = (const float*)d_in[4];   // [256]
    float* out = (float*)d_out;                   // [256][9216]

    dim3 g1(S_ / 128, 768 / 128);  // 72 x 6
    qkv_gemm<<<g1, 256>>>(x, w_qkv, b_qkv);

    dim3 g2(W_ / TQX, H_ / TQY, NH);  // 6 x 12 x 8
    natten_kernel<<<g2, 128>>>();

    dim3 g3(S_ / 128, CIN / 128);  // 72 x 2
    out_gemm<<<g3, 256>>>(w_out, b_out, out);
}

// round 2
// speedup vs baseline: 1.1330x; 1.1330x over previous
#include <cuda_runtime.h>
#include <cuda_bf16.h>

#define H_   96
#define W_   96
#define S_   9216
#define CIN  256
#define NH   8
#define DH   32

// fp32 qkv for the attention kernel: [g][s][d], g = sel*8 + h
__device__ float g_qkv[3 * NH * S_ * DH];
// bf16 split operands
__device__ __nv_bfloat16 g_xhi[S_ * CIN];   // x transposed: [s][c]
__device__ __nv_bfloat16 g_xlo[S_ * CIN];
__device__ __nv_bfloat16 g_wqhi[768 * CIN];
__device__ __nv_bfloat16 g_wqlo[768 * CIN];
__device__ __nv_bfloat16 g_wohi[CIN * CIN];
__device__ __nv_bfloat16 g_wolo[CIN * CIN];
__device__ __nv_bfloat16 g_ahi[S_ * CIN];   // attention out split: [s][c]
__device__ __nv_bfloat16 g_alo[S_ * CIN];

// ---------------------------------------------------------------------------
// helpers
// ---------------------------------------------------------------------------
__device__ __forceinline__ void cp16(void* sdst, const void* gsrc) {
    unsigned d = (unsigned)__cvta_generic_to_shared(sdst);
    asm volatile("cp.async.cg.shared.global [%0], [%1], 16;" :: "r"(d), "l"(gsrc));
}
__device__ __forceinline__ void cp_commit() {
    asm volatile("cp.async.commit_group;");
}
template<int N> __device__ __forceinline__ void cp_wait() {
    asm volatile("cp.async.wait_group %0;" :: "n"(N));
}
__device__ __forceinline__ unsigned ldu32(const __nv_bfloat16* p) {
    return *reinterpret_cast<const unsigned*>(p);
}
__device__ __forceinline__ void mma16816(float& d0, float& d1, float& d2, float& d3,
                                         unsigned a0, unsigned a1, unsigned a2, unsigned a3,
                                         unsigned b0, unsigned b1) {
    asm volatile(
        "mma.sync.aligned.m16n8k16.row.col.f32.bf16.bf16.f32 "
        "{%0,%1,%2,%3},{%4,%5,%6,%7},{%8,%9},{%0,%1,%2,%3};"
        : "+f"(d0), "+f"(d1), "+f"(d2), "+f"(d3)
        : "r"(a0), "r"(a1), "r"(a2), "r"(a3), "r"(b0), "r"(b1));
}
__device__ __forceinline__ void split_bf16(float v, __nv_bfloat16& hi, __nv_bfloat16& lo) {
    hi = __float2bfloat16_rn(v);
    lo = __float2bfloat16_rn(v - __bfloat162float(hi));
}

// ---------------------------------------------------------------------------
// prep: transpose+split x [C][S] -> xhi/xlo [S][C]
// ---------------------------------------------------------------------------
__global__ __launch_bounds__(256) void split_x_kernel(const float* __restrict__ x)
{
    __shared__ float tile[32][33];
    const int m0 = blockIdx.x * 32;   // s
    const int k0 = blockIdx.y * 32;   // c
    const int tx = threadIdx.x & 31, ty = threadIdx.x >> 5;
#pragma unroll
    for (int i = 0; i < 4; i++)
        tile[ty + 8 * i][tx] = x[(k0 + ty + 8 * i) * S_ + m0 + tx];
    __syncthreads();
#pragma unroll
    for (int i = 0; i < 4; i++) {
        int row = ty + 8 * i;
        float v = tile[tx][row];
        __nv_bfloat16 hi, lo;
        split_bf16(v, hi, lo);
        g_xhi[(m0 + row) * CIN + k0 + tx] = hi;
        g_xlo[(m0 + row) * CIN + k0 + tx] = lo;
    }
}

// prep: split both weight matrices (layouts already [n][k])
__global__ __launch_bounds__(256) void split_w_kernel(
    const float* __restrict__ wq, const float* __restrict__ wo)
{
    const int NQ = 768 * CIN;
    const int NO = CIN * CIN;
    for (int i = blockIdx.x * blockDim.x + threadIdx.x; i < NQ + NO;
         i += gridDim.x * blockDim.x) {
        __nv_bfloat16 hi, lo;
        if (i < NQ) {
            split_bf16(wq[i], hi, lo);
            g_wqhi[i] = hi; g_wqlo[i] = lo;
        } else {
            int j = i - NQ;
            split_bf16(wo[j], hi, lo);
            g_wohi[j] = hi; g_wolo[j] = lo;
        }
    }
}

// ---------------------------------------------------------------------------
// bf16x3 GEMM: C[m][n] = sum_k A[m][k]*B[n][k], M tile 128, N tile 128, K=256
// A,B split into hi/lo bf16. EPI 0: qkv scatter epilogue. EPI 1: NCHW out.
// ---------------------------------------------------------------------------
#define PITCH 24
#define NTILE 16

template<int EPI>
__global__ __launch_bounds__(256, 2) void gemm_bf16x3(
    const __nv_bfloat16* __restrict__ Ahi, const __nv_bfloat16* __restrict__ Alo,
    const __nv_bfloat16* __restrict__ Bhi, const __nv_bfloat16* __restrict__ Blo,
    const float* __restrict__ bias, float* __restrict__ Cout)
{
    __shared__ __nv_bfloat16 SA[2][2][128][PITCH];
    __shared__ __nv_bfloat16 SB[2][2][128][PITCH];

    const int bm = blockIdx.x * 128;
    const int bn = blockIdx.y * 128;
    const int tid = threadIdx.x;
    const int lane = tid & 31, wid = tid >> 5;
    const int g = lane >> 2, t4 = lane & 3;
    const int mw = (wid & 1) * 64, nw = (wid >> 1) * 32;

    const int lr = tid >> 1;          // row 0..127
    const int lc = (tid & 1) * 8;     // k chunk 0 or 8

    float acc[4][4][4];
#pragma unroll
    for (int a = 0; a < 4; a++)
#pragma unroll
        for (int b = 0; b < 4; b++)
#pragma unroll
            for (int c = 0; c < 4; c++) acc[a][b][c] = 0.f;

    // tile loader
    auto issue = [&](int t, int st) {
        int k0 = t * 16;
        cp16(&SA[st][0][lr][lc], Ahi + (size_t)(bm + lr) * CIN + k0 + lc);
        cp16(&SA[st][1][lr][lc], Alo + (size_t)(bm + lr) * CIN + k0 + lc);
        cp16(&SB[st][0][lr][lc], Bhi + (size_t)(bn + lr) * CIN + k0 + lc);
        cp16(&SB[st][1][lr][lc], Blo + (size_t)(bn + lr) * CIN + k0 + lc);
    };

    issue(0, 0); cp_commit();
    issue(1, 1); cp_commit();
    cp_wait<1>();
    __syncthreads();

    for (int t = 0; t < NTILE; t++) {
        const int st = t & 1;
        // B fragments for this tile
        unsigned bh[4][2], bl[4][2];
#pragma unroll
        for (int nt = 0; nt < 4; nt++) {
            int n = nw + 8 * nt + g;
            bh[nt][0] = ldu32(&SB[st][0][n][2 * t4]);
            bh[nt][1] = ldu32(&SB[st][0][n][2 * t4 + 8]);
            bl[nt][0] = ldu32(&SB[st][1][n][2 * t4]);
            bl[nt][1] = ldu32(&SB[st][1][n][2 * t4 + 8]);
        }
#pragma unroll
        for (int mt = 0; mt < 4; mt++) {
            int m = mw + 16 * mt + g;
            unsigned ah0 = ldu32(&SA[st][0][m][2 * t4]);
            unsigned ah1 = ldu32(&SA[st][0][m + 8][2 * t4]);
            unsigned ah2 = ldu32(&SA[st][0][m][2 * t4 + 8]);
            unsigned ah3 = ldu32(&SA[st][0][m + 8][2 * t4 + 8]);
            unsigned al0 = ldu32(&SA[st][1][m][2 * t4]);
            unsigned al1 = ldu32(&SA[st][1][m + 8][2 * t4]);
            unsigned al2 = ldu32(&SA[st][1][m][2 * t4 + 8]);
            unsigned al3 = ldu32(&SA[st][1][m + 8][2 * t4 + 8]);
#pragma unroll
            for (int nt = 0; nt < 4; nt++) {
                float* d = acc[mt][nt];
                mma16816(d[0], d[1], d[2], d[3], ah0, ah1, ah2, ah3, bh[nt][0], bh[nt][1]);
                mma16816(d[0], d[1], d[2], d[3], ah0, ah1, ah2, ah3, bl[nt][0], bl[nt][1]);
                mma16816(d[0], d[1], d[2], d[3], al0, al1, al2, al3, bh[nt][0], bh[nt][1]);
            }
        }
        __syncthreads();
        if (t + 2 < NTILE) {
            issue(t + 2, st); cp_commit();
            cp_wait<1>();
        } else {
            cp_wait<0>();
        }
        __syncthreads();
    }

    // epilogue
#pragma unroll
    for (int mt = 0; mt < 4; mt++) {
#pragma unroll
        for (int nt = 0; nt < 4; nt++) {
            int m0 = bm + mw + 16 * mt + g;
            int n0 = bn + nw + 8 * nt + 2 * t4;
            float b0 = bias[n0], b1 = bias[n0 + 1];
            float* d = acc[mt][nt];
            if (EPI == 0) {
                // scatter to g_qkv[(n>>5)][m][n&31]
                int grp = n0 >> 5, dd = n0 & 31;
                float2 v0 = make_float2(d[0] + b0, d[1] + b1);
                float2 v1 = make_float2(d[2] + b0, d[3] + b1);
                *(float2*)&g_qkv[((size_t)grp * S_ + m0) * DH + dd] = v0;
                *(float2*)&g_qkv[((size_t)grp * S_ + m0 + 8) * DH + dd] = v1;
            } else {
                Cout[(size_t)n0 * S_ + m0]           = d[0] + b0;
                Cout[(size_t)(n0 + 1) * S_ + m0]     = d[1] + b1;
                Cout[(size_t)n0 * S_ + m0 + 8]       = d[2] + b0;
                Cout[(size_t)(n0 + 1) * S_ + m0 + 8] = d[3] + b1;
            }
        }
    }
}

// ---------------------------------------------------------------------------
// Neighborhood attention (fp32), epilogue writes bf16 hi/lo split
// ---------------------------------------------------------------------------
#define TQX   16
#define TQY   8
#define WINX  22
#define WINY  14
#define NPOSW 308
#define PADP  309

__global__ __launch_bounds__(128) void natten_kernel()
{
    __shared__ float4 KVs[8 * PADP];
    const int h = blockIdx.z;
    const int qx0 = blockIdx.x * TQX, qy0 = blockIdx.y * TQY;
    const int wx0 = min(max(qx0 - 3, 0), W_ - WINX);
    const int wy0 = min(max(qy0 - 3, 0), H_ - WINY);
    const int tid = threadIdx.x;
    const int qx = qx0 + (tid & 15), qy = qy0 + (tid >> 4);
    const int s = qy * W_ + qx;

    const float* Qg = g_qkv + (h * S_ + s) * DH;
    float4 qv[8];
#pragma unroll
    for (int d4 = 0; d4 < 8; d4++) qv[d4] = *(const float4*)&Qg[d4 * 4];

    const float* Kg = g_qkv + (NH + h) * S_ * DH;
    for (int i = tid; i < NPOSW * 8; i += 128) {
        int pos = i >> 3, d4 = i & 7;
        int gy = wy0 + pos / WINX, gx = wx0 + pos % WINX;
        KVs[d4 * PADP + pos] = *(const float4*)&Kg[(gy * W_ + gx) * DH + d4 * 4];
    }
    __syncthreads();

    const int by = min(max(qy, 3), H_ - 4) - 3 - wy0;
    const int bx = min(max(qx, 3), W_ - 4) - 3 - wx0;

    float sc[49];
#pragma unroll
    for (int jy = 0; jy < 7; jy++) {
#pragma unroll
        for (int jx = 0; jx < 7; jx++) {
            int pos = (by + jy) * WINX + (bx + jx);
            float4 a = make_float4(0.f, 0.f, 0.f, 0.f);
#pragma unroll
            for (int d4 = 0; d4 < 8; d4++) {
                float4 kv = KVs[d4 * PADP + pos];
                a.x = fmaf(qv[d4].x, kv.x, a.x);
                a.y = fmaf(qv[d4].y, kv.y, a.y);
                a.z = fmaf(qv[d4].z, kv.z, a.z);
                a.w = fmaf(qv[d4].w, kv.w, a.w);
            }
            sc[jy * 7 + jx] = (a.x + a.y) + (a.z + a.w);
        }
    }

    __syncthreads();
    const float* Vg = g_qkv + (2 * NH + h) * S_ * DH;
    for (int i = tid; i < NPOSW * 8; i += 128) {
        int pos = i >> 3, d4 = i & 7;
        int gy = wy0 + pos / WINX, gx = wx0 + pos % WINX;
        KVs[d4 * PADP + pos] = *(const float4*)&Vg[(gy * W_ + gx) * DH + d4 * 4];
    }
    __syncthreads();

    const float scale = 0.17677669529663687f;
    float mx = -1e30f;
#pragma unroll
    for (int j = 0; j < 49; j++) { sc[j] *= scale; mx = fmaxf(mx, sc[j]); }
    float sum = 0.f;
#pragma unroll
    for (int j = 0; j < 49; j++) { sc[j] = __expf(sc[j] - mx); sum += sc[j]; }
    float inv = 1.0f / sum;

    float4 o[8];
#pragma unroll
    for (int d4 = 0; d4 < 8; d4++) o[d4] = make_float4(0.f, 0.f, 0.f, 0.f);
#pragma unroll
    for (int jy = 0; jy < 7; jy++) {
#pragma unroll
        for (int jx = 0; jx < 7; jx++) {
            float p = sc[jy * 7 + jx] * inv;
            int pos = (by + jy) * WINX + (bx + jx);
#pragma unroll
            for (int d4 = 0; d4 < 8; d4++) {
                float4 vv = KVs[d4 * PADP + pos];
                o[d4].x = fmaf(p, vv.x, o[d4].x);
                o[d4].y = fmaf(p, vv.y, o[d4].y);
                o[d4].z = fmaf(p, vv.z, o[d4].z);
                o[d4].w = fmaf(p, vv.w, o[d4].w);
            }
        }
    }

    // epilogue: split to bf16 hi/lo, store [s][h*32+d]
    __nv_bfloat16* ph = g_ahi + (size_t)s * CIN + h * DH;
    __nv_bfloat16* pl = g_alo + (size_t)s * CIN + h * DH;
#pragma unroll
    for (int d4 = 0; d4 < 8; d4++) {
        float vals[4] = {o[d4].x, o[d4].y, o[d4].z, o[d4].w};
#pragma unroll
        for (int j = 0; j < 4; j++) {
            __nv_bfloat16 hi, lo;
            split_bf16(vals[j], hi, lo);
            ph[d4 * 4 + j] = hi;
            pl[d4 * 4 + j] = lo;
        }
    }
}

// ---------------------------------------------------------------------------
extern "C" void kernel_launch(void* const* d_in, const int* in_sizes, int n_in,
                              void* d_out, int out_size)
{
    const float* x     = (const float*)d_in[0];   // [256][9216]
    const float* w_qkv = (const float*)d_in[1];   // [768][256]
    const float* b_qkv = (const float*)d_in[2];   // [768]
    const float* w_out = (const float*)d_in[3];   // [256][256]
    const float* b_out = (const float*)d_in[4];   // [256]
    float* out = (float*)d_out;                   // [256][9216]

    split_x_kernel<<<dim3(S_ / 32, CIN / 32), 256>>>(x);
    split_w_kernel<<<128, 256>>>(w_qkv, w_out);

    __nv_bfloat16 *xhi, *xlo, *wqhi, *wqlo, *wohi, *wolo, *ahi, *alo;
    cudaGetSymbolAddress((void**)&xhi,  g_xhi);
    cudaGetSymbolAddress((void**)&xlo,  g_xlo);
    cudaGetSymbolAddress((void**)&wqhi, g_wqhi);
    cudaGetSymbolAddress((void**)&wqlo, g_wqlo);
    cudaGetSymbolAddress((void**)&wohi, g_wohi);
    cudaGetSymbolAddress((void**)&wolo, g_wolo);
    cudaGetSymbolAddress((void**)&ahi,  g_ahi);
    cudaGetSymbolAddress((void**)&alo,  g_alo);

    gemm_bf16x3<0><<<dim3(S_ / 128, 768 / 128), 256>>>(
        xhi, xlo, wqhi, wqlo, b_qkv, nullptr);

    natten_kernel<<<dim3(W_ / TQX, H_ / TQY, NH), 128>>>();

    gemm_bf16x3<1><<<dim3(S_ / 128, CIN / 128), 256>>>(
        ahi, alo, wohi, wolo, b_out, out);
}

// round 3
// speedup vs baseline: 1.2169x; 1.0740x over previous
#include <cuda_runtime.h>
#include <cuda_bf16.h>
#include <cstdint>

#define H_   96
#define W_   96
#define S_   9216
#define CIN  256
#define NH   8
#define DH   32

// fp32 qkv for the attention kernel: [g][s][d], g = sel*8 + h
__device__ float g_qkv[3 * NH * S_ * DH];
// bf16 split operands
__device__ __nv_bfloat16 g_xhi[S_ * CIN];   // x transposed: [s][c]
__device__ __nv_bfloat16 g_xlo[S_ * CIN];
__device__ __nv_bfloat16 g_wqhi[768 * CIN];
__device__ __nv_bfloat16 g_wqlo[768 * CIN];
__device__ __nv_bfloat16 g_wohi[CIN * CIN];
__device__ __nv_bfloat16 g_wolo[CIN * CIN];
__device__ __nv_bfloat16 g_ahi[S_ * CIN];   // attention out split: [s][c]
__device__ __nv_bfloat16 g_alo[S_ * CIN];

// ---------------------------------------------------------------------------
// helpers
// ---------------------------------------------------------------------------
__device__ __forceinline__ void cp16(void* sdst, const void* gsrc) {
    unsigned d = (unsigned)__cvta_generic_to_shared(sdst);
    asm volatile("cp.async.cg.shared.global [%0], [%1], 16;" :: "r"(d), "l"(gsrc));
}
__device__ __forceinline__ void cp_commit() {
    asm volatile("cp.async.commit_group;");
}
template<int N> __device__ __forceinline__ void cp_wait() {
    asm volatile("cp.async.wait_group %0;" :: "n"(N));
}
__device__ __forceinline__ unsigned ldu32(const __nv_bfloat16* p) {
    return *reinterpret_cast<const unsigned*>(p);
}
__device__ __forceinline__ void mma16816(float& d0, float& d1, float& d2, float& d3,
                                         unsigned a0, unsigned a1, unsigned a2, unsigned a3,
                                         unsigned b0, unsigned b1) {
    asm volatile(
        "mma.sync.aligned.m16n8k16.row.col.f32.bf16.bf16.f32 "
        "{%0,%1,%2,%3},{%4,%5,%6,%7},{%8,%9},{%0,%1,%2,%3};"
        : "+f"(d0), "+f"(d1), "+f"(d2), "+f"(d3)
        : "r"(a0), "r"(a1), "r"(a2), "r"(a3), "r"(b0), "r"(b1));
}
__device__ __forceinline__ void split_bf16(float v, __nv_bfloat16& hi, __nv_bfloat16& lo) {
    hi = __float2bfloat16_rn(v);
    lo = __float2bfloat16_rn(v - __bfloat162float(hi));
}
__device__ __forceinline__ unsigned pack2bf(float x, float y) {
    __nv_bfloat162 t = __floats2bfloat162_rn(x, y);   // .x = low half
    return *reinterpret_cast<unsigned*>(&t);
}

// ---------------------------------------------------------------------------
// prep: transpose+split x [C][S] -> xhi/xlo [S][C]
// ---------------------------------------------------------------------------
__global__ __launch_bounds__(256) void split_x_kernel(const float* __restrict__ x)
{
    __shared__ float tile[32][33];
    const int m0 = blockIdx.x * 32;   // s
    const int k0 = blockIdx.y * 32;   // c
    const int tx = threadIdx.x & 31, ty = threadIdx.x >> 5;
#pragma unroll
    for (int i = 0; i < 4; i++)
        tile[ty + 8 * i][tx] = x[(k0 + ty + 8 * i) * S_ + m0 + tx];
    __syncthreads();
#pragma unroll
    for (int i = 0; i < 4; i++) {
        int row = ty + 8 * i;
        float v = tile[tx][row];
        __nv_bfloat16 hi, lo;
        split_bf16(v, hi, lo);
        g_xhi[(m0 + row) * CIN + k0 + tx] = hi;
        g_xlo[(m0 + row) * CIN + k0 + tx] = lo;
    }
}

// prep: split both weight matrices (layouts already [n][k])
__global__ __launch_bounds__(256) void split_w_kernel(
    const float* __restrict__ wq, const float* __restrict__ wo)
{
    const int NQ = 768 * CIN;
    const int NO = CIN * CIN;
    for (int i = blockIdx.x * blockDim.x + threadIdx.x; i < NQ + NO;
         i += gridDim.x * blockDim.x) {
        __nv_bfloat16 hi, lo;
        if (i < NQ) {
            split_bf16(wq[i], hi, lo);
            g_wqhi[i] = hi; g_wqlo[i] = lo;
        } else {
            int j = i - NQ;
            split_bf16(wo[j], hi, lo);
            g_wohi[j] = hi; g_wolo[j] = lo;
        }
    }
}

// ---------------------------------------------------------------------------
// bf16x3 GEMM: C[m][n] = sum_k A[m][k]*B[n][k], M tile 128, N tile 128, K=256
// ---------------------------------------------------------------------------
#define PITCH 24
#define NTILE 16

template<int EPI>
__global__ __launch_bounds__(256, 2) void gemm_bf16x3(
    const __nv_bfloat16* __restrict__ Ahi, const __nv_bfloat16* __restrict__ Alo,
    const __nv_bfloat16* __restrict__ Bhi, const __nv_bfloat16* __restrict__ Blo,
    const float* __restrict__ bias, float* __restrict__ Cout)
{
    __shared__ __nv_bfloat16 SA[2][2][128][PITCH];
    __shared__ __nv_bfloat16 SB[2][2][128][PITCH];

    const int bm = blockIdx.x * 128;
    const int bn = blockIdx.y * 128;
    const int tid = threadIdx.x;
    const int lane = tid & 31, wid = tid >> 5;
    const int g = lane >> 2, t4 = lane & 3;
    const int mw = (wid & 1) * 64, nw = (wid >> 1) * 32;

    const int lr = tid >> 1;
    const int lc = (tid & 1) * 8;

    float acc[4][4][4];
#pragma unroll
    for (int a = 0; a < 4; a++)
#pragma unroll
        for (int b = 0; b < 4; b++)
#pragma unroll
            for (int c = 0; c < 4; c++) acc[a][b][c] = 0.f;

    auto issue = [&](int t, int st) {
        int k0 = t * 16;
        cp16(&SA[st][0][lr][lc], Ahi + (size_t)(bm + lr) * CIN + k0 + lc);
        cp16(&SA[st][1][lr][lc], Alo + (size_t)(bm + lr) * CIN + k0 + lc);
        cp16(&SB[st][0][lr][lc], Bhi + (size_t)(bn + lr) * CIN + k0 + lc);
        cp16(&SB[st][1][lr][lc], Blo + (size_t)(bn + lr) * CIN + k0 + lc);
    };

    issue(0, 0); cp_commit();
    issue(1, 1); cp_commit();
    cp_wait<1>();
    __syncthreads();

    for (int t = 0; t < NTILE; t++) {
        const int st = t & 1;
        unsigned bh[4][2], bl[4][2];
#pragma unroll
        for (int nt = 0; nt < 4; nt++) {
            int n = nw + 8 * nt + g;
            bh[nt][0] = ldu32(&SB[st][0][n][2 * t4]);
            bh[nt][1] = ldu32(&SB[st][0][n][2 * t4 + 8]);
            bl[nt][0] = ldu32(&SB[st][1][n][2 * t4]);
            bl[nt][1] = ldu32(&SB[st][1][n][2 * t4 + 8]);
        }
#pragma unroll
        for (int mt = 0; mt < 4; mt++) {
            int m = mw + 16 * mt + g;
            unsigned ah0 = ldu32(&SA[st][0][m][2 * t4]);
            unsigned ah1 = ldu32(&SA[st][0][m + 8][2 * t4]);
            unsigned ah2 = ldu32(&SA[st][0][m][2 * t4 + 8]);
            unsigned ah3 = ldu32(&SA[st][0][m + 8][2 * t4 + 8]);
            unsigned al0 = ldu32(&SA[st][1][m][2 * t4]);
            unsigned al1 = ldu32(&SA[st][1][m + 8][2 * t4]);
            unsigned al2 = ldu32(&SA[st][1][m][2 * t4 + 8]);
            unsigned al3 = ldu32(&SA[st][1][m + 8][2 * t4 + 8]);
#pragma unroll
            for (int nt = 0; nt < 4; nt++) {
                float* d = acc[mt][nt];
                mma16816(d[0], d[1], d[2], d[3], ah0, ah1, ah2, ah3, bh[nt][0], bh[nt][1]);
                mma16816(d[0], d[1], d[2], d[3], ah0, ah1, ah2, ah3, bl[nt][0], bl[nt][1]);
                mma16816(d[0], d[1], d[2], d[3], al0, al1, al2, al3, bh[nt][0], bh[nt][1]);
            }
        }
        __syncthreads();
        if (t + 2 < NTILE) {
            issue(t + 2, st); cp_commit();
            cp_wait<1>();
        } else {
            cp_wait<0>();
        }
        __syncthreads();
    }

#pragma unroll
    for (int mt = 0; mt < 4; mt++) {
#pragma unroll
        for (int nt = 0; nt < 4; nt++) {
            int m0 = bm + mw + 16 * mt + g;
            int n0 = bn + nw + 8 * nt + 2 * t4;
            float b0 = bias[n0], b1 = bias[n0 + 1];
            float* d = acc[mt][nt];
            if (EPI == 0) {
                int grp = n0 >> 5, dd = n0 & 31;
                float2 v0 = make_float2(d[0] + b0, d[1] + b1);
                float2 v1 = make_float2(d[2] + b0, d[3] + b1);
                *(float2*)&g_qkv[((size_t)grp * S_ + m0) * DH + dd] = v0;
                *(float2*)&g_qkv[((size_t)grp * S_ + m0 + 8) * DH + dd] = v1;
            } else {
                Cout[(size_t)n0 * S_ + m0]           = d[0] + b0;
                Cout[(size_t)(n0 + 1) * S_ + m0]     = d[1] + b1;
                Cout[(size_t)n0 * S_ + m0 + 8]       = d[2] + b0;
                Cout[(size_t)(n0 + 1) * S_ + m0 + 8] = d[3] + b1;
            }
        }
    }
}

// ---------------------------------------------------------------------------
// MMA neighborhood attention.
// Block: 256 threads (8 warps), 16x8 query tile (128 queries), one head.
// Window 22x14 = 308 positions padded to 320. bf16x3 QK and PV; masked
// softmax in registers via a 128x320 bitmask in smem. QK fp32 accumulators
// are converted in place to packed bf16 hi/lo and reused as PV A-fragments.
// ---------------------------------------------------------------------------
#define TQX    16
#define TQY    8
#define WINX   22
#define WINY   14
#define NPOS   308
#define NW     320
#define NTN    40            // NW/8 score n-tiles
#define PQK    40            // pitch (bf16) for SQ/SK rows (dh=32 + 8 pad)
#define PV_    328           // pitch (bf16) for SV rows (320 + 8 pad)

#define SQ_ELE (128 * PQK)
#define SK_ELE (NW * PQK)
#define SV_ELE (32 * PV_)
#define NATTEN_SMEM (2 * (SQ_ELE + SK_ELE + SV_ELE) * 2 + 128 * 10 * 4)

__global__ __launch_bounds__(256, 1) void natten_mma()
{
    extern __shared__ __nv_bfloat16 sm[];
    __nv_bfloat16* sqh = sm;
    __nv_bfloat16* sql = sqh + SQ_ELE;
    __nv_bfloat16* skh = sql + SQ_ELE;
    __nv_bfloat16* skl = skh + SK_ELE;
    __nv_bfloat16* svh = skl + SK_ELE;
    __nv_bfloat16* svl = svh + SV_ELE;
    uint32_t* smask = (uint32_t*)(svl + SV_ELE);

    const int h = blockIdx.z;
    const int qx0 = blockIdx.x * TQX, qy0 = blockIdx.y * TQY;
    const int wx0 = min(max(qx0 - 3, 0), W_ - WINX);
    const int wy0 = min(max(qy0 - 3, 0), H_ - WINY);
    const int tid = threadIdx.x;
    const int lane = tid & 31, wid = tid >> 5;
    const int g = lane >> 2, t4 = lane & 3;
    const float scale = 0.17677669529663687f;  // 1/sqrt(32)

    // ---- stage Q (scaled, split) ----
    const float* Qb = g_qkv + (size_t)h * S_ * DH;
    for (int i = tid; i < 128 * 8; i += 256) {
        int m = i >> 3, d4 = (i & 7) * 4;
        int s = (qy0 + (m >> 4)) * W_ + qx0 + (m & 15);
        float4 v = *(const float4*)&Qb[(size_t)s * DH + d4];
        float vals[4] = {v.x * scale, v.y * scale, v.z * scale, v.w * scale};
#pragma unroll
        for (int j = 0; j < 4; j++) {
            __nv_bfloat16 hi, lo;
            split_bf16(vals[j], hi, lo);
            sqh[m * PQK + d4 + j] = hi;
            sql[m * PQK + d4 + j] = lo;
        }
    }
    // ---- stage K ----
    const float* Kb = g_qkv + (size_t)(NH + h) * S_ * DH;
    for (int i = tid; i < NW * 8; i += 256) {
        int p = i >> 3, d4 = (i & 7) * 4;
        float4 v = make_float4(0.f, 0.f, 0.f, 0.f);
        if (p < NPOS) {
            int gy = wy0 + p / WINX, gx = wx0 + p % WINX;
            v = *(const float4*)&Kb[(size_t)(gy * W_ + gx) * DH + d4];
        }
        float vals[4] = {v.x, v.y, v.z, v.w};
#pragma unroll
        for (int j = 0; j < 4; j++) {
            __nv_bfloat16 hi, lo;
            split_bf16(vals[j], hi, lo);
            skh[p * PQK + d4 + j] = hi;
            skl[p * PQK + d4 + j] = lo;
        }
    }
    // ---- stage V transposed: sv[d][pos] ----
    const float* Vb = g_qkv + (size_t)(2 * NH + h) * S_ * DH;
    for (int i = tid; i < NW * 8; i += 256) {
        int p = i >> 3, d4 = (i & 7) * 4;
        float4 v = make_float4(0.f, 0.f, 0.f, 0.f);
        if (p < NPOS) {
            int gy = wy0 + p / WINX, gx = wx0 + p % WINX;
            v = *(const float4*)&Vb[(size_t)(gy * W_ + gx) * DH + d4];
        }
        float vals[4] = {v.x, v.y, v.z, v.w};
#pragma unroll
        for (int j = 0; j < 4; j++) {
            __nv_bfloat16 hi, lo;
            split_bf16(vals[j], hi, lo);
            svh[(d4 + j) * PV_ + p] = hi;
            svl[(d4 + j) * PV_ + p] = lo;
        }
    }
    // ---- build mask bits: smask[m][10] over 320 window positions ----
    if (tid < 128) {
        int qy = qy0 + (tid >> 4), qx = qx0 + (tid & 15);
        int by = min(max(qy, 3), H_ - 4) - 3 - wy0;
        int bx = min(max(qx, 3), W_ - 4) - 3 - wx0;
        uint32_t w[10];
#pragma unroll
        for (int t = 0; t < 10; t++) w[t] = 0u;
#pragma unroll
        for (int jy = 0; jy < 7; jy++) {
            int base = (by + jy) * WINX + bx;
#pragma unroll
            for (int jx = 0; jx < 7; jx++) {
                int n = base + jx;
                w[n >> 5] |= 1u << (n & 31);
            }
        }
#pragma unroll
        for (int t = 0; t < 10; t++) smask[tid * 10 + t] = w[t];
    }
    __syncthreads();

    // ---- QK: warp owns rows [16*wid, 16*wid+16), all 320 cols ----
    const int m0 = wid * 16;
    unsigned qa_h[2][4], qa_l[2][4];
#pragma unroll
    for (int kc = 0; kc < 2; kc++) {
        int kb = 16 * kc;
        qa_h[kc][0] = ldu32(&sqh[(m0 + g) * PQK + kb + 2 * t4]);
        qa_h[kc][1] = ldu32(&sqh[(m0 + g + 8) * PQK + kb + 2 * t4]);
        qa_h[kc][2] = ldu32(&sqh[(m0 + g) * PQK + kb + 2 * t4 + 8]);
        qa_h[kc][3] = ldu32(&sqh[(m0 + g + 8) * PQK + kb + 2 * t4 + 8]);
        qa_l[kc][0] = ldu32(&sql[(m0 + g) * PQK + kb + 2 * t4]);
        qa_l[kc][1] = ldu32(&sql[(m0 + g + 8) * PQK + kb + 2 * t4]);
        qa_l[kc][2] = ldu32(&sql[(m0 + g) * PQK + kb + 2 * t4 + 8]);
        qa_l[kc][3] = ldu32(&sql[(m0 + g + 8) * PQK + kb + 2 * t4 + 8]);
    }

    float acc[NTN][4];
#pragma unroll
    for (int nt = 0; nt < NTN; nt++)
#pragma unroll
        for (int e = 0; e < 4; e++) acc[nt][e] = 0.f;

#pragma unroll
    for (int nt = 0; nt < NTN; nt++) {
        int n = nt * 8 + g;
        unsigned bh0 = ldu32(&skh[n * PQK + 2 * t4]);
        unsigned bh1 = ldu32(&skh[n * PQK + 2 * t4 + 8]);
        unsigned bh2 = ldu32(&skh[n * PQK + 16 + 2 * t4]);
        unsigned bh3 = ldu32(&skh[n * PQK + 16 + 2 * t4 + 8]);
        unsigned bl0 = ldu32(&skl[n * PQK + 2 * t4]);
        unsigned bl1 = ldu32(&skl[n * PQK + 2 * t4 + 8]);
        unsigned bl2 = ldu32(&skl[n * PQK + 16 + 2 * t4]);
        unsigned bl3 = ldu32(&skl[n * PQK + 16 + 2 * t4 + 8]);
        float* d = acc[nt];
        mma16816(d[0], d[1], d[2], d[3], qa_h[0][0], qa_h[0][1], qa_h[0][2], qa_h[0][3], bh0, bh1);
        mma16816(d[0], d[1], d[2], d[3], qa_h[1][0], qa_h[1][1], qa_h[1][2], qa_h[1][3], bh2, bh3);
        mma16816(d[0], d[1], d[2], d[3], qa_h[0][0], qa_h[0][1], qa_h[0][2], qa_h[0][3], bl0, bl1);
        mma16816(d[0], d[1], d[2], d[3], qa_h[1][0], qa_h[1][1], qa_h[1][2], qa_h[1][3], bl2, bl3);
        mma16816(d[0], d[1], d[2], d[3], qa_l[0][0], qa_l[0][1], qa_l[0][2], qa_l[0][3], bh0, bh1);
        mma16816(d[0], d[1], d[2], d[3], qa_l[1][0], qa_l[1][1], qa_l[1][2], qa_l[1][3], bh2, bh3);
    }

    // ---- masked softmax ----
    const int r0 = m0 + g, r1 = m0 + g + 8;   // local query rows
    uint32_t mw0[10], mw1[10];
#pragma unroll
    for (int t = 0; t < 10; t++) {
        mw0[t] = smask[r0 * 10 + t];
        mw1[t] = smask[r1 * 10 + t];
    }
    float mx0 = -1e30f, mx1 = -1e30f;
#pragma unroll
    for (int nt = 0; nt < NTN; nt++) {
        int word = nt >> 2, sh = (nt * 8) & 31;
#pragma unroll
        for (int e = 0; e < 2; e++) {
            int bit = sh + 2 * t4 + e;
            acc[nt][e]     = ((mw0[word] >> bit) & 1u) ? acc[nt][e]     : -1e30f;
            acc[nt][2 + e] = ((mw1[word] >> bit) & 1u) ? acc[nt][2 + e] : -1e30f;
            mx0 = fmaxf(mx0, acc[nt][e]);
            mx1 = fmaxf(mx1, acc[nt][2 + e]);
        }
    }
    mx0 = fmaxf(mx0, __shfl_xor_sync(0xffffffffu, mx0, 1));
    mx0 = fmaxf(mx0, __shfl_xor_sync(0xffffffffu, mx0, 2));
    mx1 = fmaxf(mx1, __shfl_xor_sync(0xffffffffu, mx1, 1));
    mx1 = fmaxf(mx1, __shfl_xor_sync(0xffffffffu, mx1, 2));

    float sum0 = 0.f, sum1 = 0.f;
#pragma unroll
    for (int nt = 0; nt < NTN; nt++) {
#pragma unroll
        for (int e = 0; e < 2; e++) {
            float p0 = __expf(acc[nt][e] - mx0);
            float p1 = __expf(acc[nt][2 + e] - mx1);
            acc[nt][e] = p0; acc[nt][2 + e] = p1;
            sum0 += p0; sum1 += p1;
        }
    }
    sum0 += __shfl_xor_sync(0xffffffffu, sum0, 1);
    sum0 += __shfl_xor_sync(0xffffffffu, sum0, 2);
    sum1 += __shfl_xor_sync(0xffffffffu, sum1, 1);
    sum1 += __shfl_xor_sync(0xffffffffu, sum1, 2);
    const float inv0 = 1.0f / sum0, inv1 = 1.0f / sum1;

    // ---- convert scores in place to packed bf16 hi/lo A-fragments ----
    // layout after: acc[nt][0] = hi(row r0 cols), acc[nt][1] = hi(row r1),
    //               acc[nt][2] = lo(row r0),      acc[nt][3] = lo(row r1)
#pragma unroll
    for (int nt = 0; nt < NTN; nt++) {
        float p00 = acc[nt][0], p01 = acc[nt][1];
        float p10 = acc[nt][2], p11 = acc[nt][3];
        unsigned h0 = pack2bf(p00, p01);
        unsigned h1 = pack2bf(p10, p11);
        float r00 = p00 - __bfloat162float(__float2bfloat16_rn(p00));
        float r01 = p01 - __bfloat162float(__float2bfloat16_rn(p01));
        float r10 = p10 - __bfloat162float(__float2bfloat16_rn(p10));
        float r11 = p11 - __bfloat162float(__float2bfloat16_rn(p11));
        acc[nt][0] = __uint_as_float(h0);
        acc[nt][1] = __uint_as_float(h1);
        acc[nt][2] = __uint_as_float(pack2bf(r00, r01));
        acc[nt][3] = __uint_as_float(pack2bf(r10, r11));
    }

    // ---- PV: o[m16][dh32] ----
    float o[4][4];
#pragma unroll
    for (int vt = 0; vt < 4; vt++)
#pragma unroll
        for (int e = 0; e < 4; e++) o[vt][e] = 0.f;

#pragma unroll
    for (int kt = 0; kt < 20; kt++) {
        unsigned ah0 = __float_as_uint(acc[2 * kt][0]);
        unsigned ah1 = __float_as_uint(acc[2 * kt][1]);
        unsigned ah2 = __float_as_uint(acc[2 * kt + 1][0]);
        unsigned ah3 = __float_as_uint(acc[2 * kt + 1][1]);
        unsigned al0 = __float_as_uint(acc[2 * kt][2]);
        unsigned al1 = __float_as_uint(acc[2 * kt][3]);
        unsigned al2 = __float_as_uint(acc[2 * kt + 1][2]);
        unsigned al3 = __float_as_uint(acc[2 * kt + 1][3]);
#pragma unroll
        for (int vt = 0; vt < 4; vt++) {
            int n = vt * 8 + g;
            unsigned bh0 = ldu32(&svh[n * PV_ + 16 * kt + 2 * t4]);
            unsigned bh1 = ldu32(&svh[n * PV_ + 16 * kt + 2 * t4 + 8]);
            unsigned bl0 = ldu32(&svl[n * PV_ + 16 * kt + 2 * t4]);
            unsigned bl1 = ldu32(&svl[n * PV_ + 16 * kt + 2 * t4 + 8]);
            float* d = o[vt];
            mma16816(d[0], d[1], d[2], d[3], ah0, ah1, ah2, ah3, bh0, bh1);
            mma16816(d[0], d[1], d[2], d[3], ah0, ah1, ah2, ah3, bl0, bl1);
            mma16816(d[0], d[1], d[2], d[3], al0, al1, al2, al3, bh0, bh1);
        }
    }

    // ---- epilogue: normalize, split, store to g_ahi/g_alo [s][h*32+d] ----
    {
        int my0 = qy0 + (r0 >> 4), mx0i = qx0 + (r0 & 15);
        int my1 = qy0 + (r1 >> 4), mx1i = qx0 + (r1 & 15);
        size_t s0 = (size_t)(my0 * W_ + mx0i) * CIN + h * DH;
        size_t s1 = (size_t)(my1 * W_ + mx1i) * CIN + h * DH;
#pragma unroll
        for (int vt = 0; vt < 4; vt++) {
            int c = vt * 8 + 2 * t4;
            float f00 = o[vt][0] * inv0, f01 = o[vt][1] * inv0;
            float f10 = o[vt][2] * inv1, f11 = o[vt][3] * inv1;
            __nv_bfloat16 h00, l00, h01, l01, h10, l10, h11, l11;
            split_bf16(f00, h00, l00); split_bf16(f01, h01, l01);
            split_bf16(f10, h10, l10); split_bf16(f11, h11, l11);
            *(unsigned*)&g_ahi[s0 + c] = ((unsigned)*(unsigned short*)&h01 << 16) | *(unsigned short*)&h00;
            *(unsigned*)&g_alo[s0 + c] = ((unsigned)*(unsigned short*)&l01 << 16) | *(unsigned short*)&l00;
            *(unsigned*)&g_ahi[s1 + c] = ((unsigned)*(unsigned short*)&h11 << 16) | *(unsigned short*)&h10;
            *(unsigned*)&g_alo[s1 + c] = ((unsigned)*(unsigned short*)&l11 << 16) | *(unsigned short*)&l10;
        }
    }
}

// ---------------------------------------------------------------------------
extern "C" void kernel_launch(void* const* d_in, const int* in_sizes, int n_in,
                              void* d_out, int out_size)
{
    const float* x     = (const float*)d_in[0];   // [256][9216]
    const float* w_qkv = (const float*)d_in[1];   // [768][256]
    const float* b_qkv = (const float*)d_in[2];   // [768]
    const float* w_out = (const float*)d_in[3];   // [256][256]
    const float* b_out = (const float*)d_in[4];   // [256]
    float* out = (float*)d_out;                   // [256][9216]

    cudaFuncSetAttribute(natten_mma,
                         cudaFuncAttributeMaxDynamicSharedMemorySize, NATTEN_SMEM);

    split_x_kernel<<<dim3(S_ / 32, CIN / 32), 256>>>(x);
    split_w_kernel<<<128, 256>>>(w_qkv, w_out);

    __nv_bfloat16 *xhi, *xlo, *wqhi, *wqlo, *wohi, *wolo, *ahi, *alo;
    cudaGetSymbolAddress((void**)&xhi,  g_xhi);
    cudaGetSymbolAddress((void**)&xlo,  g_xlo);
    cudaGetSymbolAddress((void**)&wqhi, g_wqhi);
    cudaGetSymbolAddress((void**)&wqlo, g_wqlo);
    cudaGetSymbolAddress((void**)&wohi, g_wohi);
    cudaGetSymbolAddress((void**)&wolo, g_wolo);
    cudaGetSymbolAddress((void**)&ahi,  g_ahi);
    cudaGetSymbolAddress((void**)&alo,  g_alo);

    gemm_bf16x3<0><<<dim3(S_ / 128, 768 / 128), 256>>>(
        xhi, xlo, wqhi, wqlo, b_qkv, nullptr);

    natten_mma<<<dim3(W_ / TQX, H_ / TQY, NH), 256, NATTEN_SMEM>>>();

    gemm_bf16x3<1><<<dim3(S_ / 128, CIN / 128), 256>>>(
        ahi, alo, wohi, wolo, b_out, out);
}

// round 4
// speedup vs baseline: 1.7156x; 1.4098x over previous
#include <cuda_runtime.h>
#include <cuda_bf16.h>
#include <cstdint>

#define H_   96
#define W_   96
#define S_   9216
#define CIN  256
#define NH   8
#define DH   32

// fp32 qkv for the attention kernel: [g][s][d], g = sel*8 + h
__device__ float g_qkv[3 * NH * S_ * DH];
// bf16 split operands
__device__ __nv_bfloat16 g_xhi[S_ * CIN];   // x transposed: [s][c]
__device__ __nv_bfloat16 g_xlo[S_ * CIN];
__device__ __nv_bfloat16 g_wqhi[768 * CIN];
__device__ __nv_bfloat16 g_wqlo[768 * CIN];
__device__ __nv_bfloat16 g_wohi[CIN * CIN];
__device__ __nv_bfloat16 g_wolo[CIN * CIN];
__device__ __nv_bfloat16 g_ahi[S_ * CIN];   // attention out split: [s][c]
__device__ __nv_bfloat16 g_alo[S_ * CIN];

// ---------------------------------------------------------------------------
// helpers
// ---------------------------------------------------------------------------
__device__ __forceinline__ void cp16(void* sdst, const void* gsrc) {
    unsigned d = (unsigned)__cvta_generic_to_shared(sdst);
    asm volatile("cp.async.cg.shared.global [%0], [%1], 16;" :: "r"(d), "l"(gsrc));
}
__device__ __forceinline__ void cp_commit() {
    asm volatile("cp.async.commit_group;");
}
template<int N> __device__ __forceinline__ void cp_wait() {
    asm volatile("cp.async.wait_group %0;" :: "n"(N));
}
__device__ __forceinline__ unsigned ldu32(const __nv_bfloat16* p) {
    return *reinterpret_cast<const unsigned*>(p);
}
__device__ __forceinline__ void mma16816(float& d0, float& d1, float& d2, float& d3,
                                         unsigned a0, unsigned a1, unsigned a2, unsigned a3,
                                         unsigned b0, unsigned b1) {
    asm volatile(
        "mma.sync.aligned.m16n8k16.row.col.f32.bf16.bf16.f32 "
        "{%0,%1,%2,%3},{%4,%5,%6,%7},{%8,%9},{%0,%1,%2,%3};"
        : "+f"(d0), "+f"(d1), "+f"(d2), "+f"(d3)
        : "r"(a0), "r"(a1), "r"(a2), "r"(a3), "r"(b0), "r"(b1));
}
__device__ __forceinline__ void split_bf16(float v, __nv_bfloat16& hi, __nv_bfloat16& lo) {
    hi = __float2bfloat16_rn(v);
    lo = __float2bfloat16_rn(v - __bfloat162float(hi));
}
__device__ __forceinline__ unsigned pack2bf(float x, float y) {
    __nv_bfloat162 t = __floats2bfloat162_rn(x, y);   // .x = low half
    return *reinterpret_cast<unsigned*>(&t);
}

// ---------------------------------------------------------------------------
// prep: transpose+split x [C][S] -> xhi/xlo [S][C]
// ---------------------------------------------------------------------------
__global__ __launch_bounds__(256) void split_x_kernel(const float* __restrict__ x)
{
    __shared__ float tile[32][33];
    const int m0 = blockIdx.x * 32;   // s
    const int k0 = blockIdx.y * 32;   // c
    const int tx = threadIdx.x & 31, ty = threadIdx.x >> 5;
#pragma unroll
    for (int i = 0; i < 4; i++)
        tile[ty + 8 * i][tx] = x[(k0 + ty + 8 * i) * S_ + m0 + tx];
    __syncthreads();
#pragma unroll
    for (int i = 0; i < 4; i++) {
        int row = ty + 8 * i;
        float v = tile[tx][row];
        __nv_bfloat16 hi, lo;
        split_bf16(v, hi, lo);
        g_xhi[(m0 + row) * CIN + k0 + tx] = hi;
        g_xlo[(m0 + row) * CIN + k0 + tx] = lo;
    }
}

// prep: split both weight matrices (layouts already [n][k])
__global__ __launch_bounds__(256) void split_w_kernel(
    const float* __restrict__ wq, const float* __restrict__ wo)
{
    const int NQ = 768 * CIN;
    const int NO = CIN * CIN;
    for (int i = blockIdx.x * blockDim.x + threadIdx.x; i < NQ + NO;
         i += gridDim.x * blockDim.x) {
        __nv_bfloat16 hi, lo;
        if (i < NQ) {
            split_bf16(wq[i], hi, lo);
            g_wqhi[i] = hi; g_wqlo[i] = lo;
        } else {
            int j = i - NQ;
            split_bf16(wo[j], hi, lo);
            g_wohi[j] = hi; g_wolo[j] = lo;
        }
    }
}

// ---------------------------------------------------------------------------
// bf16x3 GEMM: C[m][n] = sum_k A[m][k]*B[n][k], M tile 128, N tile 128, K=256
// ---------------------------------------------------------------------------
#define PITCH 24
#define NTILE 16

template<int EPI>
__global__ __launch_bounds__(256, 2) void gemm_bf16x3(
    const __nv_bfloat16* __restrict__ Ahi, const __nv_bfloat16* __restrict__ Alo,
    const __nv_bfloat16* __restrict__ Bhi, const __nv_bfloat16* __restrict__ Blo,
    const float* __restrict__ bias, float* __restrict__ Cout)
{
    __shared__ __nv_bfloat16 SA[2][2][128][PITCH];
    __shared__ __nv_bfloat16 SB[2][2][128][PITCH];

    const int bm = blockIdx.x * 128;
    const int bn = blockIdx.y * 128;
    const int tid = threadIdx.x;
    const int lane = tid & 31, wid = tid >> 5;
    const int g = lane >> 2, t4 = lane & 3;
    const int mw = (wid & 1) * 64, nw = (wid >> 1) * 32;

    const int lr = tid >> 1;
    const int lc = (tid & 1) * 8;

    float acc[4][4][4];
#pragma unroll
    for (int a = 0; a < 4; a++)
#pragma unroll
        for (int b = 0; b < 4; b++)
#pragma unroll
            for (int c = 0; c < 4; c++) acc[a][b][c] = 0.f;

    auto issue = [&](int t, int st) {
        int k0 = t * 16;
        cp16(&SA[st][0][lr][lc], Ahi + (size_t)(bm + lr) * CIN + k0 + lc);
        cp16(&SA[st][1][lr][lc], Alo + (size_t)(bm + lr) * CIN + k0 + lc);
        cp16(&SB[st][0][lr][lc], Bhi + (size_t)(bn + lr) * CIN + k0 + lc);
        cp16(&SB[st][1][lr][lc], Blo + (size_t)(bn + lr) * CIN + k0 + lc);
    };

    issue(0, 0); cp_commit();
    issue(1, 1); cp_commit();
    cp_wait<1>();
    __syncthreads();

    for (int t = 0; t < NTILE; t++) {
        const int st = t & 1;
        unsigned bh[4][2], bl[4][2];
#pragma unroll
        for (int nt = 0; nt < 4; nt++) {
            int n = nw + 8 * nt + g;
            bh[nt][0] = ldu32(&SB[st][0][n][2 * t4]);
            bh[nt][1] = ldu32(&SB[st][0][n][2 * t4 + 8]);
            bl[nt][0] = ldu32(&SB[st][1][n][2 * t4]);
            bl[nt][1] = ldu32(&SB[st][1][n][2 * t4 + 8]);
        }
#pragma unroll
        for (int mt = 0; mt < 4; mt++) {
            int m = mw + 16 * mt + g;
            unsigned ah0 = ldu32(&SA[st][0][m][2 * t4]);
            unsigned ah1 = ldu32(&SA[st][0][m + 8][2 * t4]);
            unsigned ah2 = ldu32(&SA[st][0][m][2 * t4 + 8]);
            unsigned ah3 = ldu32(&SA[st][0][m + 8][2 * t4 + 8]);
            unsigned al0 = ldu32(&SA[st][1][m][2 * t4]);
            unsigned al1 = ldu32(&SA[st][1][m + 8][2 * t4]);
            unsigned al2 = ldu32(&SA[st][1][m][2 * t4 + 8]);
            unsigned al3 = ldu32(&SA[st][1][m + 8][2 * t4 + 8]);
#pragma unroll
            for (int nt = 0; nt < 4; nt++) {
                float* d = acc[mt][nt];
                mma16816(d[0], d[1], d[2], d[3], ah0, ah1, ah2, ah3, bh[nt][0], bh[nt][1]);
                mma16816(d[0], d[1], d[2], d[3], ah0, ah1, ah2, ah3, bl[nt][0], bl[nt][1]);
                mma16816(d[0], d[1], d[2], d[3], al0, al1, al2, al3, bh[nt][0], bh[nt][1]);
            }
        }
        __syncthreads();
        if (t + 2 < NTILE) {
            issue(t + 2, st); cp_commit();
            cp_wait<1>();
        } else {
            cp_wait<0>();
        }
        __syncthreads();
    }

#pragma unroll
    for (int mt = 0; mt < 4; mt++) {
#pragma unroll
        for (int nt = 0; nt < 4; nt++) {
            int m0 = bm + mw + 16 * mt + g;
            int n0 = bn + nw + 8 * nt + 2 * t4;
            float b0 = bias[n0], b1 = bias[n0 + 1];
            float* d = acc[mt][nt];
            if (EPI == 0) {
                int grp = n0 >> 5, dd = n0 & 31;
                float2 v0 = make_float2(d[0] + b0, d[1] + b1);
                float2 v1 = make_float2(d[2] + b0, d[3] + b1);
                *(float2*)&g_qkv[((size_t)grp * S_ + m0) * DH + dd] = v0;
                *(float2*)&g_qkv[((size_t)grp * S_ + m0 + 8) * DH + dd] = v1;
            } else {
                Cout[(size_t)n0 * S_ + m0]           = d[0] + b0;
                Cout[(size_t)(n0 + 1) * S_ + m0]     = d[1] + b1;
                Cout[(size_t)n0 * S_ + m0 + 8]       = d[2] + b0;
                Cout[(size_t)(n0 + 1) * S_ + m0 + 8] = d[3] + b1;
            }
        }
    }
}

// ---------------------------------------------------------------------------
// MMA neighborhood attention, v2.
// Block: 256 threads (8 warps), 16x8 query tile per block (one head).
// Each warp owns an 8x2 query subtile (16 queries = one m16 fragment,
// row r -> query (y = r>>3, x = r&7)). Warp key window: 16x8 = 128 cols
// (14x8 real + 2 pad). Block stages K (22x14 union window) in smem, QK MMA,
// then restages V transposed into the SAME buffer, PV MMA.
// Masks are pure ALU range checks; no bitmask staging. Q loaded from gmem.
// ---------------------------------------------------------------------------
#define TQX    16
#define TQY    8
#define WINX   22
#define WINY   14
#define NPOS   308
#define PQK    40            // K row pitch (bf16): dh 32 + 8
#define PVP    328           // V^T row pitch (bf16): 320 + 8
#define SKSPL  (NPOS * PQK)  // 12320 el per split
#define SVSPL  (32 * PVP)    // 10496 el per split
#define NATTEN_SMEM (2 * SKSPL * 2)   // 49280 B (K phase is the max)

__global__ __launch_bounds__(256, 2) void natten_mma()
{
    extern __shared__ __nv_bfloat16 sm[];
    __nv_bfloat16* skh = sm;
    __nv_bfloat16* skl = sm + SKSPL;
    __nv_bfloat16* svh = sm;             // aliased after barrier
    __nv_bfloat16* svl = sm + SVSPL;

    const int h = blockIdx.z;
    const int qx0 = blockIdx.x * TQX, qy0 = blockIdx.y * TQY;
    const int wx0 = min(max(qx0 - 3, 0), W_ - WINX);
    const int wy0 = min(max(qy0 - 3, 0), H_ - WINY);
    const int tid = threadIdx.x;
    const int lane = tid & 31, wid = tid >> 5;
    const int g = lane >> 2, t4 = lane & 3;
    const float scale = 0.17677669529663687f;  // 1/sqrt(32)

    // warp query subtile origin
    const int wxq = (wid & 1) * 8;        // x offset in block tile
    const int wyq = (wid >> 1) * 2;       // y offset
    const int qxg = qx0 + wxq + g;        // this thread's query x (rows r0,r1)
    const int qyg0 = qy0 + wyq, qyg1 = qyg0 + 1;

    // warp window origin inside the block window (x even for aligned LDS)
    const int cxs = min(max(qx0 + wxq, 3), W_ - 4);
    const int cys = min(max(qyg0, 3), H_ - 4);
    const int bx0 = min((cxs - 3 - wx0) & ~1, 6);
    const int by0 = min(cys - 3 - wy0, 6);

    // per-thread valid ranges (mask): jx in [vx,vx+7), jy row0 [vy0,vy0+7), row1 [vy1,..)
    const int cx = min(max(qxg, 3), W_ - 4);
    const int cy0 = min(max(qyg0, 3), H_ - 4);
    const int cy1 = min(max(qyg1, 3), H_ - 4);
    const int vx  = cx - 3 - wx0 - bx0;
    const int vy0 = cy0 - 3 - wy0 - by0;
    const int vy1 = cy1 - 3 - wy0 - by0;

    // ---- load Q fragments straight from gmem (fp32), scale + split ----
    const float* Qb = g_qkv + (size_t)h * S_ * DH;
    unsigned qa_h[2][4], qa_l[2][4];
    {
        const size_t s0 = (size_t)(qyg0 * W_ + qxg) * DH;
        const size_t s1 = (size_t)(qyg1 * W_ + qxg) * DH;
#pragma unroll
        for (int kc = 0; kc < 2; kc++) {
            float2 u0 = *(const float2*)&Qb[s0 + kc * 16 + 2 * t4];
            float2 u1 = *(const float2*)&Qb[s1 + kc * 16 + 2 * t4];
            float2 w0 = *(const float2*)&Qb[s0 + kc * 16 + 8 + 2 * t4];
            float2 w1 = *(const float2*)&Qb[s1 + kc * 16 + 8 + 2 * t4];
            u0.x *= scale; u0.y *= scale; u1.x *= scale; u1.y *= scale;
            w0.x *= scale; w0.y *= scale; w1.x *= scale; w1.y *= scale;
            unsigned h0 = pack2bf(u0.x, u0.y);
            unsigned h1 = pack2bf(u1.x, u1.y);
            unsigned h2 = pack2bf(w0.x, w0.y);
            unsigned h3 = pack2bf(w1.x, w1.y);
            qa_h[kc][0] = h0; qa_h[kc][1] = h1; qa_h[kc][2] = h2; qa_h[kc][3] = h3;
            qa_l[kc][0] = pack2bf(u0.x - __bfloat162float(__float2bfloat16_rn(u0.x)),
                                  u0.y - __bfloat162float(__float2bfloat16_rn(u0.y)));
            qa_l[kc][1] = pack2bf(u1.x - __bfloat162float(__float2bfloat16_rn(u1.x)),
                                  u1.y - __bfloat162float(__float2bfloat16_rn(u1.y)));
            qa_l[kc][2] = pack2bf(w0.x - __bfloat162float(__float2bfloat16_rn(w0.x)),
                                  w0.y - __bfloat162float(__float2bfloat16_rn(w0.y)));
            qa_l[kc][3] = pack2bf(w1.x - __bfloat162float(__float2bfloat16_rn(w1.x)),
                                  w1.y - __bfloat162float(__float2bfloat16_rn(w1.y)));
        }
    }

    // ---- stage K: [pos][dh] hi/lo ----
    const float* Kb = g_qkv + (size_t)(NH + h) * S_ * DH;
    for (int i = tid; i < NPOS * 8; i += 256) {
        int p = i >> 3, d4 = (i & 7) * 4;
        int gy = wy0 + p / WINX, gx = wx0 + p % WINX;
        float4 v = *(const float4*)&Kb[(size_t)(gy * W_ + gx) * DH + d4];
        float vals[4] = {v.x, v.y, v.z, v.w};
#pragma unroll
        for (int j = 0; j < 4; j++) {
            __nv_bfloat16 hi, lo;
            split_bf16(vals[j], hi, lo);
            skh[p * PQK + d4 + j] = hi;
            skl[p * PQK + d4 + j] = lo;
        }
    }
    __syncthreads();

    // ---- QK MMA: 16 n-tiles of 8 over the warp's 16x8 window ----
    float acc[16][4];
#pragma unroll
    for (int nt = 0; nt < 16; nt++)
#pragma unroll
        for (int e = 0; e < 4; e++) acc[nt][e] = 0.f;

#pragma unroll
    for (int nt = 0; nt < 16; nt++) {
        const int jy = nt >> 1;
        const int jx = (nt & 1) ? (g + 8) : g;
        const int pos = (by0 + jy) * WINX + bx0 + jx;
        const __nv_bfloat16* kh = &skh[pos * PQK];
        const __nv_bfloat16* kl = &skl[pos * PQK];
        unsigned bh0 = ldu32(kh + 2 * t4);
        unsigned bh1 = ldu32(kh + 2 * t4 + 8);
        unsigned bh2 = ldu32(kh + 16 + 2 * t4);
        unsigned bh3 = ldu32(kh + 24 + 2 * t4);
        unsigned bl0 = ldu32(kl + 2 * t4);
        unsigned bl1 = ldu32(kl + 2 * t4 + 8);
        unsigned bl2 = ldu32(kl + 16 + 2 * t4);
        unsigned bl3 = ldu32(kl + 24 + 2 * t4);
        float* d = acc[nt];
        mma16816(d[0], d[1], d[2], d[3], qa_h[0][0], qa_h[0][1], qa_h[0][2], qa_h[0][3], bh0, bh1);
        mma16816(d[0], d[1], d[2], d[3], qa_h[1][0], qa_h[1][1], qa_h[1][2], qa_h[1][3], bh2, bh3);
        mma16816(d[0], d[1], d[2], d[3], qa_h[0][0], qa_h[0][1], qa_h[0][2], qa_h[0][3], bl0, bl1);
        mma16816(d[0], d[1], d[2], d[3], qa_h[1][0], qa_h[1][1], qa_h[1][2], qa_h[1][3], bl2, bl3);
        mma16816(d[0], d[1], d[2], d[3], qa_l[0][0], qa_l[0][1], qa_l[0][2], qa_l[0][3], bh0, bh1);
        mma16816(d[0], d[1], d[2], d[3], qa_l[1][0], qa_l[1][1], qa_l[1][2], qa_l[1][3], bh2, bh3);
    }
    __syncthreads();   // all QK smem reads done; buffer is free for V

    // ---- stage V transposed: [dh][pos] hi/lo (aliases K buffer) ----
    const float* Vb = g_qkv + (size_t)(2 * NH + h) * S_ * DH;
    for (int i = tid; i < NPOS * 8; i += 256) {
        int p = i >> 3, d4 = (i & 7) * 4;
        int gy = wy0 + p / WINX, gx = wx0 + p % WINX;
        float4 v = *(const float4*)&Vb[(size_t)(gy * W_ + gx) * DH + d4];
        float vals[4] = {v.x, v.y, v.z, v.w};
#pragma unroll
        for (int j = 0; j < 4; j++) {
            __nv_bfloat16 hi, lo;
            split_bf16(vals[j], hi, lo);
            svh[(d4 + j) * PVP + p] = hi;
            svl[(d4 + j) * PVP + p] = lo;
        }
    }

    // ---- masked softmax (registers only; overlaps with V staging) ----
    // acc[nt] = {r0 c(n0), r0 c(n0+1), r1 c(n0), r1 c(n0+1)}, n0 = nt*8+2*t4
    float mx0 = -1e30f, mx1 = -1e30f;
#pragma unroll
    for (int nt = 0; nt < 16; nt++) {
        const int jy = nt >> 1;
        const int jxb = (nt & 1) * 8 + 2 * t4;
#pragma unroll
        for (int e = 0; e < 2; e++) {
            const int jx = jxb + e;
            bool okx = (unsigned)(jx - vx) < 7u;
            bool ok0 = okx && ((unsigned)(jy - vy0) < 7u);
            bool ok1 = okx && ((unsigned)(jy - vy1) < 7u);
            acc[nt][e]     = ok0 ? acc[nt][e]     : -1e30f;
            acc[nt][2 + e] = ok1 ? acc[nt][2 + e] : -1e30f;
            mx0 = fmaxf(mx0, acc[nt][e]);
            mx1 = fmaxf(mx1, acc[nt][2 + e]);
        }
    }
    mx0 = fmaxf(mx0, __shfl_xor_sync(0xffffffffu, mx0, 1));
    mx0 = fmaxf(mx0, __shfl_xor_sync(0xffffffffu, mx0, 2));
    mx1 = fmaxf(mx1, __shfl_xor_sync(0xffffffffu, mx1, 1));
    mx1 = fmaxf(mx1, __shfl_xor_sync(0xffffffffu, mx1, 2));

    float sum0 = 0.f, sum1 = 0.f;
#pragma unroll
    for (int nt = 0; nt < 16; nt++) {
#pragma unroll
        for (int e = 0; e < 2; e++) {
            float p0 = __expf(acc[nt][e] - mx0);
            float p1 = __expf(acc[nt][2 + e] - mx1);
            acc[nt][e] = p0; acc[nt][2 + e] = p1;
            sum0 += p0; sum1 += p1;
        }
    }
    sum0 += __shfl_xor_sync(0xffffffffu, sum0, 1);
    sum0 += __shfl_xor_sync(0xffffffffu, sum0, 2);
    sum1 += __shfl_xor_sync(0xffffffffu, sum1, 1);
    sum1 += __shfl_xor_sync(0xffffffffu, sum1, 2);
    const float inv0 = 1.0f / sum0, inv1 = 1.0f / sum1;

    // ---- convert P in place to packed bf16 hi/lo A-fragments ----
#pragma unroll
    for (int nt = 0; nt < 16; nt++) {
        float p00 = acc[nt][0], p01 = acc[nt][1];
        float p10 = acc[nt][2], p11 = acc[nt][3];
        unsigned hh0 = pack2bf(p00, p01);
        unsigned hh1 = pack2bf(p10, p11);
        float r00 = p00 - __bfloat162float(__float2bfloat16_rn(p00));
        float r01 = p01 - __bfloat162float(__float2bfloat16_rn(p01));
        float r10 = p10 - __bfloat162float(__float2bfloat16_rn(p10));
        float r11 = p11 - __bfloat162float(__float2bfloat16_rn(p11));
        acc[nt][0] = __uint_as_float(hh0);
        acc[nt][1] = __uint_as_float(hh1);
        acc[nt][2] = __uint_as_float(pack2bf(r00, r01));
        acc[nt][3] = __uint_as_float(pack2bf(r10, r11));
    }
    __syncthreads();   // V staged

    // ---- PV MMA: k = 128 window positions (8 k-tiles), n = dh 32 (4 vt) ----
    float o[4][4];
#pragma unroll
    for (int vt = 0; vt < 4; vt++)
#pragma unroll
        for (int e = 0; e < 4; e++) o[vt][e] = 0.f;

#pragma unroll
    for (int kt = 0; kt < 8; kt++) {
        unsigned ah0 = __float_as_uint(acc[2 * kt][0]);
        unsigned ah1 = __float_as_uint(acc[2 * kt][1]);
        unsigned ah2 = __float_as_uint(acc[2 * kt + 1][0]);
        unsigned ah3 = __float_as_uint(acc[2 * kt + 1][1]);
        unsigned al0 = __float_as_uint(acc[2 * kt][2]);
        unsigned al1 = __float_as_uint(acc[2 * kt][3]);
        unsigned al2 = __float_as_uint(acc[2 * kt + 1][2]);
        unsigned al3 = __float_as_uint(acc[2 * kt + 1][3]);
        const int prow = (by0 + kt) * WINX + bx0;   // window row base, bx0 even
#pragma unroll
        for (int vt = 0; vt < 4; vt++) {
            const int n = vt * 8 + g;
            const __nv_bfloat16* vh = &svh[n * PVP + prow];
            const __nv_bfloat16* vl = &svl[n * PVP + prow];
            unsigned bh0 = ldu32(vh + 2 * t4);
            unsigned bh1 = ldu32(vh + 8 + 2 * t4);
            unsigned bl0 = ldu32(vl + 2 * t4);
            unsigned bl1 = ldu32(vl + 8 + 2 * t4);
            float* d = o[vt];
            mma16816(d[0], d[1], d[2], d[3], ah0, ah1, ah2, ah3, bh0, bh1);
            mma16816(d[0], d[1], d[2], d[3], ah0, ah1, ah2, ah3, bl0, bl1);
            mma16816(d[0], d[1], d[2], d[3], al0, al1, al2, al3, bh0, bh1);
        }
    }

    // ---- epilogue: normalize, split, store [s][h*32+d] ----
    {
        size_t s0 = (size_t)(qyg0 * W_ + qxg) * CIN + h * DH;
        size_t s1 = (size_t)(qyg1 * W_ + qxg) * CIN + h * DH;
#pragma unroll
        for (int vt = 0; vt < 4; vt++) {
            int c = vt * 8 + 2 * t4;
            float f00 = o[vt][0] * inv0, f01 = o[vt][1] * inv0;
            float f10 = o[vt][2] * inv1, f11 = o[vt][3] * inv1;
            __nv_bfloat16 h00, l00, h01, l01, h10, l10, h11, l11;
            split_bf16(f00, h00, l00); split_bf16(f01, h01, l01);
            split_bf16(f10, h10, l10); split_bf16(f11, h11, l11);
            *(unsigned*)&g_ahi[s0 + c] = ((unsigned)*(unsigned short*)&h01 << 16) | *(unsigned short*)&h00;
            *(unsigned*)&g_alo[s0 + c] = ((unsigned)*(unsigned short*)&l01 << 16) | *(unsigned short*)&l00;
            *(unsigned*)&g_ahi[s1 + c] = ((unsigned)*(unsigned short*)&h11 << 16) | *(unsigned short*)&h10;
            *(unsigned*)&g_alo[s1 + c] = ((unsigned)*(unsigned short*)&l11 << 16) | *(unsigned short*)&l10;
        }
    }
}

// ---------------------------------------------------------------------------
extern "C" void kernel_launch(void* const* d_in, const int* in_sizes, int n_in,
                              void* d_out, int out_size)
{
    const float* x     = (const float*)d_in[0];   // [256][9216]
    const float* w_qkv = (const float*)d_in[1];   // [768][256]
    const float* b_qkv = (const float*)d_in[2];   // [768]
    const float* w_out = (const float*)d_in[3];   // [256][256]
    const float* b_out = (const float*)d_in[4];   // [256]
    float* out = (float*)d_out;                   // [256][9216]

    cudaFuncSetAttribute(natten_mma,
                         cudaFuncAttributeMaxDynamicSharedMemorySize, NATTEN_SMEM);

    split_x_kernel<<<dim3(S_ / 32, CIN / 32), 256>>>(x);
    split_w_kernel<<<128, 256>>>(w_qkv, w_out);

    __nv_bfloat16 *xhi, *xlo, *wqhi, *wqlo, *wohi, *wolo, *ahi, *alo;
    cudaGetSymbolAddress((void**)&xhi,  g_xhi);
    cudaGetSymbolAddress((void**)&xlo,  g_xlo);
    cudaGetSymbolAddress((void**)&wqhi, g_wqhi);
    cudaGetSymbolAddress((void**)&wqlo, g_wqlo);
    cudaGetSymbolAddress((void**)&wohi, g_wohi);
    cudaGetSymbolAddress((void**)&wolo, g_wolo);
    cudaGetSymbolAddress((void**)&ahi,  g_ahi);
    cudaGetSymbolAddress((void**)&alo,  g_alo);

    gemm_bf16x3<0><<<dim3(S_ / 128, 768 / 128), 256>>>(
        xhi, xlo, wqhi, wqlo, b_qkv, nullptr);

    natten_mma<<<dim3(W_ / TQX, H_ / TQY, NH), 256, NATTEN_SMEM>>>();

    gemm_bf16x3<1><<<dim3(S_ / 128, CIN / 128), 256>>>(
        ahi, alo, wohi, wolo, b_out, out);
}

// round 5
// speedup vs baseline: 1.8303x; 1.0669x over previous
#include <cuda_runtime.h>
#include <cuda_bf16.h>
#include <cstdint>

#define H_   96
#define W_   96
#define S_   9216
#define CIN  256
#define NH   8
#define DH   32

// attention operands produced by qkv GEMM
__device__ float         g_q[NH * S_ * DH];            // fp32 Q
__device__ __nv_bfloat16 g_khi[NH * S_ * DH];          // K split
__device__ __nv_bfloat16 g_klo[NH * S_ * DH];
__device__ __nv_bfloat16 g_vhi[NH * S_ * DH];          // V split
__device__ __nv_bfloat16 g_vlo[NH * S_ * DH];
// bf16 split GEMM inputs
__device__ __nv_bfloat16 g_xhi[S_ * CIN];   // x transposed: [s][c]
__device__ __nv_bfloat16 g_xlo[S_ * CIN];
__device__ __nv_bfloat16 g_wqhi[768 * CIN];
__device__ __nv_bfloat16 g_wqlo[768 * CIN];
__device__ __nv_bfloat16 g_wohi[CIN * CIN];
__device__ __nv_bfloat16 g_wolo[CIN * CIN];
__device__ __nv_bfloat16 g_ahi[S_ * CIN];   // attention out split: [s][c]
__device__ __nv_bfloat16 g_alo[S_ * CIN];

// ---------------------------------------------------------------------------
// helpers
// ---------------------------------------------------------------------------
__device__ __forceinline__ void cp16(void* sdst, const void* gsrc) {
    unsigned d = (unsigned)__cvta_generic_to_shared(sdst);
    asm volatile("cp.async.cg.shared.global [%0], [%1], 16;" :: "r"(d), "l"(gsrc));
}
__device__ __forceinline__ void cp_commit() {
    asm volatile("cp.async.commit_group;");
}
template<int N> __device__ __forceinline__ void cp_wait() {
    asm volatile("cp.async.wait_group %0;" :: "n"(N));
}
__device__ __forceinline__ unsigned ldu32(const __nv_bfloat16* p) {
    return *reinterpret_cast<const unsigned*>(p);
}
__device__ __forceinline__ void mma16816(float& d0, float& d1, float& d2, float& d3,
                                         unsigned a0, unsigned a1, unsigned a2, unsigned a3,
                                         unsigned b0, unsigned b1) {
    asm volatile(
        "mma.sync.aligned.m16n8k16.row.col.f32.bf16.bf16.f32 "
        "{%0,%1,%2,%3},{%4,%5,%6,%7},{%8,%9},{%0,%1,%2,%3};"
        : "+f"(d0), "+f"(d1), "+f"(d2), "+f"(d3)
        : "r"(a0), "r"(a1), "r"(a2), "r"(a3), "r"(b0), "r"(b1));
}
__device__ __forceinline__ void ldmx4(unsigned& r0, unsigned& r1, unsigned& r2, unsigned& r3,
                                      const __nv_bfloat16* p) {
    unsigned a = (unsigned)__cvta_generic_to_shared(p);
    asm volatile("ldmatrix.sync.aligned.m8n8.x4.shared.b16 {%0,%1,%2,%3}, [%4];"
                 : "=r"(r0), "=r"(r1), "=r"(r2), "=r"(r3) : "r"(a));
}
__device__ __forceinline__ void ldmx4t(unsigned& r0, unsigned& r1, unsigned& r2, unsigned& r3,
                                       const __nv_bfloat16* p) {
    unsigned a = (unsigned)__cvta_generic_to_shared(p);
    asm volatile("ldmatrix.sync.aligned.m8n8.x4.trans.shared.b16 {%0,%1,%2,%3}, [%4];"
                 : "=r"(r0), "=r"(r1), "=r"(r2), "=r"(r3) : "r"(a));
}
__device__ __forceinline__ void split_bf16(float v, __nv_bfloat16& hi, __nv_bfloat16& lo) {
    hi = __float2bfloat16_rn(v);
    lo = __float2bfloat16_rn(v - __bfloat162float(hi));
}
__device__ __forceinline__ float bf_res(float v) {
    return v - __bfloat162float(__float2bfloat16_rn(v));
}
__device__ __forceinline__ unsigned pack2bf(float x, float y) {
    __nv_bfloat162 t = __floats2bfloat162_rn(x, y);   // .x = low half
    return *reinterpret_cast<unsigned*>(&t);
}

// ---------------------------------------------------------------------------
// prep: transpose+split x [C][S] -> xhi/xlo [S][C]
// ---------------------------------------------------------------------------
__global__ __launch_bounds__(256) void split_x_kernel(const float* __restrict__ x)
{
    __shared__ float tile[32][33];
    const int m0 = blockIdx.x * 32;   // s
    const int k0 = blockIdx.y * 32;   // c
    const int tx = threadIdx.x & 31, ty = threadIdx.x >> 5;
#pragma unroll
    for (int i = 0; i < 4; i++)
        tile[ty + 8 * i][tx] = x[(k0 + ty + 8 * i) * S_ + m0 + tx];
    __syncthreads();
#pragma unroll
    for (int i = 0; i < 4; i++) {
        int row = ty + 8 * i;
        float v = tile[tx][row];
        __nv_bfloat16 hi, lo;
        split_bf16(v, hi, lo);
        g_xhi[(m0 + row) * CIN + k0 + tx] = hi;
        g_xlo[(m0 + row) * CIN + k0 + tx] = lo;
    }
}

// prep: split both weight matrices (layouts already [n][k])
__global__ __launch_bounds__(256) void split_w_kernel(
    const float* __restrict__ wq, const float* __restrict__ wo)
{
    const int NQ = 768 * CIN;
    const int NO = CIN * CIN;
    for (int i = blockIdx.x * blockDim.x + threadIdx.x; i < NQ + NO;
         i += gridDim.x * blockDim.x) {
        __nv_bfloat16 hi, lo;
        if (i < NQ) {
            split_bf16(wq[i], hi, lo);
            g_wqhi[i] = hi; g_wqlo[i] = lo;
        } else {
            int j = i - NQ;
            split_bf16(wo[j], hi, lo);
            g_wohi[j] = hi; g_wolo[j] = lo;
        }
    }
}

// ---------------------------------------------------------------------------
// bf16x3 GEMM: C[m][n] = sum_k A[m][k]*B[n][k], M tile 128, N tile 128, K=256
// EPI 0: write q fp32 / k,v bf16-split. EPI 1: NCHW fp32 output.
// ---------------------------------------------------------------------------
#define PITCH 24
#define NTILE 16

template<int EPI>
__global__ __launch_bounds__(256, 2) void gemm_bf16x3(
    const __nv_bfloat16* __restrict__ Ahi, const __nv_bfloat16* __restrict__ Alo,
    const __nv_bfloat16* __restrict__ Bhi, const __nv_bfloat16* __restrict__ Blo,
    const float* __restrict__ bias, float* __restrict__ Cout)
{
    __shared__ __nv_bfloat16 SA[2][2][128][PITCH];
    __shared__ __nv_bfloat16 SB[2][2][128][PITCH];

    const int bm = blockIdx.x * 128;
    const int bn = blockIdx.y * 128;
    const int tid = threadIdx.x;
    const int lane = tid & 31, wid = tid >> 5;
    const int g = lane >> 2, t4 = lane & 3;
    const int mw = (wid & 1) * 64, nw = (wid >> 1) * 32;

    const int lr = tid >> 1;
    const int lc = (tid & 1) * 8;

    float acc[4][4][4];
#pragma unroll
    for (int a = 0; a < 4; a++)
#pragma unroll
        for (int b = 0; b < 4; b++)
#pragma unroll
            for (int c = 0; c < 4; c++) acc[a][b][c] = 0.f;

    auto issue = [&](int t, int st) {
        int k0 = t * 16;
        cp16(&SA[st][0][lr][lc], Ahi + (size_t)(bm + lr) * CIN + k0 + lc);
        cp16(&SA[st][1][lr][lc], Alo + (size_t)(bm + lr) * CIN + k0 + lc);
        cp16(&SB[st][0][lr][lc], Bhi + (size_t)(bn + lr) * CIN + k0 + lc);
        cp16(&SB[st][1][lr][lc], Blo + (size_t)(bn + lr) * CIN + k0 + lc);
    };

    issue(0, 0); cp_commit();
    issue(1, 1); cp_commit();
    cp_wait<1>();
    __syncthreads();

    for (int t = 0; t < NTILE; t++) {
        const int st = t & 1;
        unsigned bh[4][2], bl[4][2];
#pragma unroll
        for (int nt = 0; nt < 4; nt++) {
            int n = nw + 8 * nt + g;
            bh[nt][0] = ldu32(&SB[st][0][n][2 * t4]);
            bh[nt][1] = ldu32(&SB[st][0][n][2 * t4 + 8]);
            bl[nt][0] = ldu32(&SB[st][1][n][2 * t4]);
            bl[nt][1] = ldu32(&SB[st][1][n][2 * t4 + 8]);
        }
#pragma unroll
        for (int mt = 0; mt < 4; mt++) {
            int m = mw + 16 * mt + g;
            unsigned ah0 = ldu32(&SA[st][0][m][2 * t4]);
            unsigned ah1 = ldu32(&SA[st][0][m + 8][2 * t4]);
            unsigned ah2 = ldu32(&SA[st][0][m][2 * t4 + 8]);
            unsigned ah3 = ldu32(&SA[st][0][m + 8][2 * t4 + 8]);
            unsigned al0 = ldu32(&SA[st][1][m][2 * t4]);
            unsigned al1 = ldu32(&SA[st][1][m + 8][2 * t4]);
            unsigned al2 = ldu32(&SA[st][1][m][2 * t4 + 8]);
            unsigned al3 = ldu32(&SA[st][1][m + 8][2 * t4 + 8]);
#pragma unroll
            for (int nt = 0; nt < 4; nt++) {
                float* d = acc[mt][nt];
                mma16816(d[0], d[1], d[2], d[3], ah0, ah1, ah2, ah3, bh[nt][0], bh[nt][1]);
                mma16816(d[0], d[1], d[2], d[3], ah0, ah1, ah2, ah3, bl[nt][0], bl[nt][1]);
                mma16816(d[0], d[1], d[2], d[3], al0, al1, al2, al3, bh[nt][0], bh[nt][1]);
            }
        }
        __syncthreads();
        if (t + 2 < NTILE) {
            issue(t + 2, st); cp_commit();
            cp_wait<1>();
        } else {
            cp_wait<0>();
        }
        __syncthreads();
    }

#pragma unroll
    for (int mt = 0; mt < 4; mt++) {
#pragma unroll
        for (int nt = 0; nt < 4; nt++) {
            int m0 = bm + mw + 16 * mt + g;
            int n0 = bn + nw + 8 * nt + 2 * t4;
            float b0 = bias[n0], b1 = bias[n0 + 1];
            float* d = acc[mt][nt];
            float v0 = d[0] + b0, v1 = d[1] + b1;
            float v2 = d[2] + b0, v3 = d[3] + b1;
            if (EPI == 0) {
                int sel = n0 >> 8;
                int hh = (n0 >> 5) & 7;
                int dd = n0 & 31;
                size_t i0 = ((size_t)hh * S_ + m0) * DH + dd;
                size_t i1 = i0 + 8 * DH;
                if (sel == 0) {
                    *(float2*)&g_q[i0] = make_float2(v0, v1);
                    *(float2*)&g_q[i1] = make_float2(v2, v3);
                } else if (sel == 1) {
                    *(unsigned*)&g_khi[i0] = pack2bf(v0, v1);
                    *(unsigned*)&g_klo[i0] = pack2bf(bf_res(v0), bf_res(v1));
                    *(unsigned*)&g_khi[i1] = pack2bf(v2, v3);
                    *(unsigned*)&g_klo[i1] = pack2bf(bf_res(v2), bf_res(v3));
                } else {
                    *(unsigned*)&g_vhi[i0] = pack2bf(v0, v1);
                    *(unsigned*)&g_vlo[i0] = pack2bf(bf_res(v0), bf_res(v1));
                    *(unsigned*)&g_vhi[i1] = pack2bf(v2, v3);
                    *(unsigned*)&g_vlo[i1] = pack2bf(bf_res(v2), bf_res(v3));
                }
            } else {
                Cout[(size_t)n0 * S_ + m0]           = v0;
                Cout[(size_t)(n0 + 1) * S_ + m0]     = v1;
                Cout[(size_t)n0 * S_ + m0 + 8]       = v2;
                Cout[(size_t)(n0 + 1) * S_ + m0 + 8] = v3;
            }
        }
    }
}

// ---------------------------------------------------------------------------
// MMA neighborhood attention, v3.
// 256 threads / 8 warps, 16x8 query tile per block, one head. Warp owns an
// 8x2 query subtile (one m16 fragment). Block window 22x14 = 308 positions.
// K and V windows staged by cp.async straight from pre-split bf16 gmem
// (K group 0, V group 1 -> V loads overlap QK compute). Fragments loaded
// with ldmatrix.x4 (K) / ldmatrix.x4.trans (V, natural [pos][d] layout).
// ---------------------------------------------------------------------------
#define TQX    16
#define TQY    8
#define WINX   22
#define NPOS   308
#define PQK    40                    // row pitch (bf16): 32 + 8 pad
#define SK_ELE (NPOS * PQK)          // 12320 els per array
#define NATTEN_SMEM (4 * SK_ELE * 2) // 98560 B

__global__ __launch_bounds__(256, 2) void natten_mma()
{
    extern __shared__ __nv_bfloat16 sm[];
    __nv_bfloat16* skh = sm;
    __nv_bfloat16* skl = sm + SK_ELE;
    __nv_bfloat16* svh = sm + 2 * SK_ELE;
    __nv_bfloat16* svl = sm + 3 * SK_ELE;

    const int h = blockIdx.z;
    const int qx0 = blockIdx.x * TQX, qy0 = blockIdx.y * TQY;
    const int wx0 = min(max(qx0 - 3, 0), W_ - WINX);
    const int wy0 = min(max(qy0 - 3, 0), H_ - 14);
    const int tid = threadIdx.x;
    const int lane = tid & 31, wid = tid >> 5;
    const int g = lane >> 2, t4 = lane & 3;
    const int lrow = lane & 7, lmat = lane >> 3;
    const float scale = 0.17677669529663687f;  // 1/sqrt(32)

    const size_t hb = (size_t)h * S_ * DH;

    // ---- stage K then V via cp.async (2 groups) ----
    {
        const __nv_bfloat16* Kh = g_khi + hb;
        const __nv_bfloat16* Kl = g_klo + hb;
        for (int c = tid; c < NPOS * 4; c += 256) {
            int p = c >> 2, off = (c & 3) * 8;
            int gy = wy0 + p / WINX, gx = wx0 + p % WINX;
            size_t gi = (size_t)(gy * W_ + gx) * DH + off;
            cp16(&skh[p * PQK + off], Kh + gi);
            cp16(&skl[p * PQK + off], Kl + gi);
        }
        cp_commit();
        const __nv_bfloat16* Vh = g_vhi + hb;
        const __nv_bfloat16* Vl = g_vlo + hb;
        for (int c = tid; c < NPOS * 4; c += 256) {
            int p = c >> 2, off = (c & 3) * 8;
            int gy = wy0 + p / WINX, gx = wx0 + p % WINX;
            size_t gi = (size_t)(gy * W_ + gx) * DH + off;
            cp16(&svh[p * PQK + off], Vh + gi);
            cp16(&svl[p * PQK + off], Vl + gi);
        }
        cp_commit();
    }

    // warp query subtile origin
    const int wxq = (wid & 1) * 8;
    const int wyq = (wid >> 1) * 2;
    const int qxg = qx0 + wxq + g;
    const int qyg0 = qy0 + wyq, qyg1 = qyg0 + 1;

    // warp window origin inside the block window
    const int cxs = min(max(qx0 + wxq, 3), W_ - 4);
    const int cys = min(max(qyg0, 3), H_ - 4);
    const int bx0 = min((cxs - 3 - wx0) & ~1, 6);
    const int by0 = min(cys - 3 - wy0, 6);

    // per-thread valid ranges (mask)
    const int cx = min(max(qxg, 3), W_ - 4);
    const int cy0 = min(max(qyg0, 3), H_ - 4);
    const int cy1 = min(max(qyg1, 3), H_ - 4);
    const int vx  = cx - 3 - wx0 - bx0;
    const int vy0 = cy0 - 3 - wy0 - by0;
    const int vy1 = cy1 - 3 - wy0 - by0;

    // ---- Q fragments from gmem fp32 (overlaps cp.async) ----
    const float* Qb = g_q + hb;
    unsigned qa_h[2][4], qa_l[2][4];
    {
        const size_t s0 = (size_t)(qyg0 * W_ + qxg) * DH;
        const size_t s1 = (size_t)(qyg1 * W_ + qxg) * DH;
#pragma unroll
        for (int kc = 0; kc < 2; kc++) {
            float2 u0 = *(const float2*)&Qb[s0 + kc * 16 + 2 * t4];
            float2 u1 = *(const float2*)&Qb[s1 + kc * 16 + 2 * t4];
            float2 w0 = *(const float2*)&Qb[s0 + kc * 16 + 8 + 2 * t4];
            float2 w1 = *(const float2*)&Qb[s1 + kc * 16 + 8 + 2 * t4];
            u0.x *= scale; u0.y *= scale; u1.x *= scale; u1.y *= scale;
            w0.x *= scale; w0.y *= scale; w1.x *= scale; w1.y *= scale;
            qa_h[kc][0] = pack2bf(u0.x, u0.y);
            qa_h[kc][1] = pack2bf(u1.x, u1.y);
            qa_h[kc][2] = pack2bf(w0.x, w0.y);
            qa_h[kc][3] = pack2bf(w1.x, w1.y);
            qa_l[kc][0] = pack2bf(bf_res(u0.x), bf_res(u0.y));
            qa_l[kc][1] = pack2bf(bf_res(u1.x), bf_res(u1.y));
            qa_l[kc][2] = pack2bf(bf_res(w0.x), bf_res(w0.y));
            qa_l[kc][3] = pack2bf(bf_res(w1.x), bf_res(w1.y));
        }
    }

    cp_wait<1>();     // K staged (V may still be in flight)
    __syncthreads();

    // ---- QK MMA: 16 n-tiles of 8 over the warp's 8x16 window ----
    const int kcol = (lmat & 1) * 8 + (lmat >> 1) * 16;   // ldmatrix col for K
    float acc[16][4];
#pragma unroll
    for (int nt = 0; nt < 16; nt++)
#pragma unroll
        for (int e = 0; e < 4; e++) acc[nt][e] = 0.f;

#pragma unroll
    for (int nt = 0; nt < 16; nt++) {
        const int pos0 = (by0 + (nt >> 1)) * WINX + bx0 + (nt & 1) * 8;
        unsigned bh0, bh1, bh2, bh3, bl0, bl1, bl2, bl3;
        ldmx4(bh0, bh1, bh2, bh3, &skh[(pos0 + lrow) * PQK + kcol]);
        ldmx4(bl0, bl1, bl2, bl3, &skl[(pos0 + lrow) * PQK + kcol]);
        float* d = acc[nt];
        mma16816(d[0], d[1], d[2], d[3], qa_h[0][0], qa_h[0][1], qa_h[0][2], qa_h[0][3], bh0, bh1);
        mma16816(d[0], d[1], d[2], d[3], qa_h[1][0], qa_h[1][1], qa_h[1][2], qa_h[1][3], bh2, bh3);
        mma16816(d[0], d[1], d[2], d[3], qa_h[0][0], qa_h[0][1], qa_h[0][2], qa_h[0][3], bl0, bl1);
        mma16816(d[0], d[1], d[2], d[3], qa_h[1][0], qa_h[1][1], qa_h[1][2], qa_h[1][3], bl2, bl3);
        mma16816(d[0], d[1], d[2], d[3], qa_l[0][0], qa_l[0][1], qa_l[0][2], qa_l[0][3], bh0, bh1);
        mma16816(d[0], d[1], d[2], d[3], qa_l[1][0], qa_l[1][1], qa_l[1][2], qa_l[1][3], bh2, bh3);
    }

    // ---- masked softmax (registers only) ----
    float mx0 = -1e30f, mx1 = -1e30f;
#pragma unroll
    for (int nt = 0; nt < 16; nt++) {
        const int jy = nt >> 1;
        const int jxb = (nt & 1) * 8 + 2 * t4;
#pragma unroll
        for (int e = 0; e < 2; e++) {
            const int jx = jxb + e;
            bool okx = (unsigned)(jx - vx) < 7u;
            bool ok0 = okx && ((unsigned)(jy - vy0) < 7u);
            bool ok1 = okx && ((unsigned)(jy - vy1) < 7u);
            acc[nt][e]     = ok0 ? acc[nt][e]     : -1e30f;
            acc[nt][2 + e] = ok1 ? acc[nt][2 + e] : -1e30f;
            mx0 = fmaxf(mx0, acc[nt][e]);
            mx1 = fmaxf(mx1, acc[nt][2 + e]);
        }
    }
    mx0 = fmaxf(mx0, __shfl_xor_sync(0xffffffffu, mx0, 1));
    mx0 = fmaxf(mx0, __shfl_xor_sync(0xffffffffu, mx0, 2));
    mx1 = fmaxf(mx1, __shfl_xor_sync(0xffffffffu, mx1, 1));
    mx1 = fmaxf(mx1, __shfl_xor_sync(0xffffffffu, mx1, 2));

    float sum0 = 0.f, sum1 = 0.f;
#pragma unroll
    for (int nt = 0; nt < 16; nt++) {
#pragma unroll
        for (int e = 0; e < 2; e++) {
            float p0 = __expf(acc[nt][e] - mx0);
            float p1 = __expf(acc[nt][2 + e] - mx1);
            acc[nt][e] = p0; acc[nt][2 + e] = p1;
            sum0 += p0; sum1 += p1;
        }
    }
    sum0 += __shfl_xor_sync(0xffffffffu, sum0, 1);
    sum0 += __shfl_xor_sync(0xffffffffu, sum0, 2);
    sum1 += __shfl_xor_sync(0xffffffffu, sum1, 1);
    sum1 += __shfl_xor_sync(0xffffffffu, sum1, 2);
    const float inv0 = 1.0f / sum0, inv1 = 1.0f / sum1;

    // ---- convert P in place to packed bf16 hi/lo A-fragments ----
#pragma unroll
    for (int nt = 0; nt < 16; nt++) {
        float p00 = acc[nt][0], p01 = acc[nt][1];
        float p10 = acc[nt][2], p11 = acc[nt][3];
        unsigned hh0 = pack2bf(p00, p01);
        unsigned hh1 = pack2bf(p10, p11);
        unsigned ll0 = pack2bf(bf_res(p00), bf_res(p01));
        unsigned ll1 = pack2bf(bf_res(p10), bf_res(p11));
        acc[nt][0] = __uint_as_float(hh0);
        acc[nt][1] = __uint_as_float(hh1);
        acc[nt][2] = __uint_as_float(ll0);
        acc[nt][3] = __uint_as_float(ll1);
    }

    cp_wait<0>();     // V staged
    __syncthreads();

    // ---- PV MMA: 8 k-tiles of 16 positions, n = dh 32 via ldmatrix.trans ----
    float o[4][4];
#pragma unroll
    for (int vt = 0; vt < 4; vt++)
#pragma unroll
        for (int e = 0; e < 4; e++) o[vt][e] = 0.f;

    const int vrow = (lmat & 1) * 8 + lrow;     // ldmatrix row offset for V
    const int vmat = (lmat >> 1) * 8;           // col sub-offset
#pragma unroll
    for (int kt = 0; kt < 8; kt++) {
        const int prow = (by0 + kt) * WINX + bx0;
        unsigned ah0 = __float_as_uint(acc[2 * kt][0]);
        unsigned ah1 = __float_as_uint(acc[2 * kt][1]);
        unsigned ah2 = __float_as_uint(acc[2 * kt + 1][0]);
        unsigned ah3 = __float_as_uint(acc[2 * kt + 1][1]);
        unsigned al0 = __float_as_uint(acc[2 * kt][2]);
        unsigned al1 = __float_as_uint(acc[2 * kt][3]);
        unsigned al2 = __float_as_uint(acc[2 * kt + 1][2]);
        unsigned al3 = __float_as_uint(acc[2 * kt + 1][3]);
#pragma unroll
        for (int half = 0; half < 2; half++) {
            unsigned bh0, bh1, bh2, bh3, bl0, bl1, bl2, bl3;
            const int col = half * 16 + vmat;
            ldmx4t(bh0, bh1, bh2, bh3, &svh[(prow + vrow) * PQK + col]);
            ldmx4t(bl0, bl1, bl2, bl3, &svl[(prow + vrow) * PQK + col]);
            float* d0 = o[2 * half];
            float* d1 = o[2 * half + 1];
            mma16816(d0[0], d0[1], d0[2], d0[3], ah0, ah1, ah2, ah3, bh0, bh1);
            mma16816(d0[0], d0[1], d0[2], d0[3], ah0, ah1, ah2, ah3, bl0, bl1);
            mma16816(d0[0], d0[1], d0[2], d0[3], al0, al1, al2, al3, bh0, bh1);
            mma16816(d1[0], d1[1], d1[2], d1[3], ah0, ah1, ah2, ah3, bh2, bh3);
            mma16816(d1[0], d1[1], d1[2], d1[3], ah0, ah1, ah2, ah3, bl2, bl3);
            mma16816(d1[0], d1[1], d1[2], d1[3], al0, al1, al2, al3, bh2, bh3);
        }
    }

    // ---- epilogue: normalize, split, store [s][h*32+d] ----
    {
        size_t s0 = (size_t)(qyg0 * W_ + qxg) * CIN + h * DH;
        size_t s1 = (size_t)(qyg1 * W_ + qxg) * CIN + h * DH;
#pragma unroll
        for (int vt = 0; vt < 4; vt++) {
            int c = vt * 8 + 2 * t4;
            float f00 = o[vt][0] * inv0, f01 = o[vt][1] * inv0;
            float f10 = o[vt][2] * inv1, f11 = o[vt][3] * inv1;
            *(unsigned*)&g_ahi[s0 + c] = pack2bf(f00, f01);
            *(unsigned*)&g_alo[s0 + c] = pack2bf(bf_res(f00), bf_res(f01));
            *(unsigned*)&g_ahi[s1 + c] = pack2bf(f10, f11);
            *(unsigned*)&g_alo[s1 + c] = pack2bf(bf_res(f10), bf_res(f11));
        }
    }
}

// ---------------------------------------------------------------------------
extern "C" void kernel_launch(void* const* d_in, const int* in_sizes, int n_in,
                              void* d_out, int out_size)
{
    const float* x     = (const float*)d_in[0];   // [256][9216]
    const float* w_qkv = (const float*)d_in[1];   // [768][256]
    const float* b_qkv = (const float*)d_in[2];   // [768]
    const float* w_out = (const float*)d_in[3];   // [256][256]
    const float* b_out = (const float*)d_in[4];   // [256]
    float* out = (float*)d_out;                   // [256][9216]

    cudaFuncSetAttribute(natten_mma,
                         cudaFuncAttributeMaxDynamicSharedMemorySize, NATTEN_SMEM);

    split_x_kernel<<<dim3(S_ / 32, CIN / 32), 256>>>(x);
    split_w_kernel<<<128, 256>>>(w_qkv, w_out);

    __nv_bfloat16 *xhi, *xlo, *wqhi, *wqlo, *wohi, *wolo, *ahi, *alo;
    cudaGetSymbolAddress((void**)&xhi,  g_xhi);
    cudaGetSymbolAddress((void**)&xlo,  g_xlo);
    cudaGetSymbolAddress((void**)&wqhi, g_wqhi);
    cudaGetSymbolAddress((void**)&wqlo, g_wqlo);
    cudaGetSymbolAddress((void**)&wohi, g_wohi);
    cudaGetSymbolAddress((void**)&wolo, g_wolo);
    cudaGetSymbolAddress((void**)&ahi,  g_ahi);
    cudaGetSymbolAddress((void**)&alo,  g_alo);

    gemm_bf16x3<0><<<dim3(S_ / 128, 768 / 128), 256>>>(
        xhi, xlo, wqhi, wqlo, b_qkv, nullptr);

    natten_mma<<<dim3(W_ / TQX, H_ / TQY, NH), 256, NATTEN_SMEM>>>();

    gemm_bf16x3<1><<<dim3(S_ / 128, CIN / 128), 256>>>(
        ahi, alo, wohi, wolo, b_out, out);
}

// round 6
// speedup vs baseline: 1.9948x; 1.0899x over previous
#include <cuda_runtime.h>
#include <cuda_bf16.h>
#include <cstdint>

#define H_   96
#define W_   96
#define S_   9216
#define CIN  256
#define NH   8
#define DH   32

// attention operands produced by qkv GEMM
__device__ float         g_q[NH * S_ * DH];            // fp32 Q
__device__ __nv_bfloat16 g_khi[NH * S_ * DH];          // K split
__device__ __nv_bfloat16 g_klo[NH * S_ * DH];
__device__ __nv_bfloat16 g_vhi[NH * S_ * DH];          // V split
__device__ __nv_bfloat16 g_vlo[NH * S_ * DH];
// bf16 split GEMM inputs
__device__ __nv_bfloat16 g_xhi[S_ * CIN];   // x transposed: [s][c]
__device__ __nv_bfloat16 g_xlo[S_ * CIN];
__device__ __nv_bfloat16 g_wqhi[768 * CIN];
__device__ __nv_bfloat16 g_wqlo[768 * CIN];
__device__ __nv_bfloat16 g_wohi[CIN * CIN];
__device__ __nv_bfloat16 g_wolo[CIN * CIN];
__device__ __nv_bfloat16 g_ahi[S_ * CIN];   // attention out split: [s][c]
__device__ __nv_bfloat16 g_alo[S_ * CIN];

// ---------------------------------------------------------------------------
// helpers
// ---------------------------------------------------------------------------
__device__ __forceinline__ void cp16(void* sdst, const void* gsrc) {
    unsigned d = (unsigned)__cvta_generic_to_shared(sdst);
    asm volatile("cp.async.cg.shared.global [%0], [%1], 16;" :: "r"(d), "l"(gsrc));
}
__device__ __forceinline__ void cp_commit() {
    asm volatile("cp.async.commit_group;");
}
template<int N> __device__ __forceinline__ void cp_wait() {
    asm volatile("cp.async.wait_group %0;" :: "n"(N));
}
__device__ __forceinline__ void mma16816(float& d0, float& d1, float& d2, float& d3,
                                         unsigned a0, unsigned a1, unsigned a2, unsigned a3,
                                         unsigned b0, unsigned b1) {
    asm volatile(
        "mma.sync.aligned.m16n8k16.row.col.f32.bf16.bf16.f32 "
        "{%0,%1,%2,%3},{%4,%5,%6,%7},{%8,%9},{%0,%1,%2,%3};"
        : "+f"(d0), "+f"(d1), "+f"(d2), "+f"(d3)
        : "r"(a0), "r"(a1), "r"(a2), "r"(a3), "r"(b0), "r"(b1));
}
__device__ __forceinline__ void ldmx4(unsigned& r0, unsigned& r1, unsigned& r2, unsigned& r3,
                                      const __nv_bfloat16* p) {
    unsigned a = (unsigned)__cvta_generic_to_shared(p);
    asm volatile("ldmatrix.sync.aligned.m8n8.x4.shared.b16 {%0,%1,%2,%3}, [%4];"
                 : "=r"(r0), "=r"(r1), "=r"(r2), "=r"(r3) : "r"(a));
}
__device__ __forceinline__ void ldmx4t(unsigned& r0, unsigned& r1, unsigned& r2, unsigned& r3,
                                       const __nv_bfloat16* p) {
    unsigned a = (unsigned)__cvta_generic_to_shared(p);
    asm volatile("ldmatrix.sync.aligned.m8n8.x4.trans.shared.b16 {%0,%1,%2,%3}, [%4];"
                 : "=r"(r0), "=r"(r1), "=r"(r2), "=r"(r3) : "r"(a));
}
__device__ __forceinline__ void split_bf16(float v, __nv_bfloat16& hi, __nv_bfloat16& lo) {
    hi = __float2bfloat16_rn(v);
    lo = __float2bfloat16_rn(v - __bfloat162float(hi));
}
__device__ __forceinline__ float bf_res(float v) {
    return v - __bfloat162float(__float2bfloat16_rn(v));
}
__device__ __forceinline__ unsigned pack2bf(float x, float y) {
    __nv_bfloat162 t = __floats2bfloat162_rn(x, y);   // .x = low half
    return *reinterpret_cast<unsigned*>(&t);
}

// ---------------------------------------------------------------------------
// prep (merged): blocks [0, 2304): transpose+split x [C][S] -> xhi/xlo [S][C]
//                blocks [2304, 2368): split both weight matrices
// ---------------------------------------------------------------------------
#define NBX 2304   // (S_/32) * (CIN/32)

__global__ __launch_bounds__(256) void split_all_kernel(
    const float* __restrict__ x, const float* __restrict__ wq,
    const float* __restrict__ wo)
{
    __shared__ float tile[32][33];
    if (blockIdx.x < NBX) {
        const int m0 = (blockIdx.x % (S_ / 32)) * 32;   // s
        const int k0 = (blockIdx.x / (S_ / 32)) * 32;   // c
        const int tx = threadIdx.x & 31, ty = threadIdx.x >> 5;
#pragma unroll
        for (int i = 0; i < 4; i++)
            tile[ty + 8 * i][tx] = x[(k0 + ty + 8 * i) * S_ + m0 + tx];
        __syncthreads();
#pragma unroll
        for (int i = 0; i < 4; i++) {
            int row = ty + 8 * i;
            float v = tile[tx][row];
            __nv_bfloat16 hi, lo;
            split_bf16(v, hi, lo);
            g_xhi[(m0 + row) * CIN + k0 + tx] = hi;
            g_xlo[(m0 + row) * CIN + k0 + tx] = lo;
        }
    } else {
        const int NQ = 768 * CIN;
        const int NO = CIN * CIN;
        const int bid = blockIdx.x - NBX;
        for (int i = bid * 256 + threadIdx.x; i < NQ + NO; i += 64 * 256) {
            __nv_bfloat16 hi, lo;
            if (i < NQ) {
                split_bf16(wq[i], hi, lo);
                g_wqhi[i] = hi; g_wqlo[i] = lo;
            } else {
                int j = i - NQ;
                split_bf16(wo[j], hi, lo);
                g_wohi[j] = hi; g_wolo[j] = lo;
            }
        }
    }
}

// ---------------------------------------------------------------------------
// bf16x3 GEMM: C[m][n] = sum_k A[m][k]*B[n][k], M tile 128, N tile BN, K=256.
// Fragments via ldmatrix.x4 (pitch 24 = 48B row stride: conflict-free).
// EPI 0: write q fp32 / k,v bf16-split (BN=128). EPI 1: NCHW fp32 (BN=64).
// ---------------------------------------------------------------------------
#define PITCH 24
#define NTILE 16

template<int BN, int EPI>
__global__ __launch_bounds__(256, 2) void gemm_bf16x3(
    const __nv_bfloat16* __restrict__ Ahi, const __nv_bfloat16* __restrict__ Alo,
    const __nv_bfloat16* __restrict__ Bhi, const __nv_bfloat16* __restrict__ Blo,
    const float* __restrict__ bias, float* __restrict__ Cout)
{
    constexpr int NNT = BN / 32;         // n-tiles (of 8) per warp
    __shared__ __nv_bfloat16 SA[2][2][128][PITCH];
    __shared__ __nv_bfloat16 SB[2][2][BN][PITCH];

    const int bm = blockIdx.x * 128;
    const int bn = blockIdx.y * BN;
    const int tid = threadIdx.x;
    const int lane = tid & 31, wid = tid >> 5;
    const int g = lane >> 2, t4 = lane & 3;
    const int mw = (wid & 1) * 64;
    const int nw = (wid >> 1) * (BN / 4);

    // ldmatrix per-lane offsets
    const int arow = (lane & 7) + ((lane >> 3) & 1) * 8;   // + m base
    const int acol = (lane >> 4) * 8;
    const int brow = (lane & 7) + (lane >> 4) * 8;         // + n base
    const int bcol = ((lane >> 3) & 1) * 8;

    // loaders
    const int lr = tid >> 1;             // A row 0..127
    const int lc = (tid & 1) * 8;
    const int br_ = tid >> 1;            // B row (BN=128: 0..127; BN=64 uses tid<128)
    const int bc_ = (tid & 1) * 8;

    float acc[4][NNT][4];
#pragma unroll
    for (int a = 0; a < 4; a++)
#pragma unroll
        for (int b = 0; b < NNT; b++)
#pragma unroll
            for (int c = 0; c < 4; c++) acc[a][b][c] = 0.f;

    auto issue = [&](int t, int st) {
        int k0 = t * 16;
        cp16(&SA[st][0][lr][lc], Ahi + (size_t)(bm + lr) * CIN + k0 + lc);
        cp16(&SA[st][1][lr][lc], Alo + (size_t)(bm + lr) * CIN + k0 + lc);
        if (BN == 128 || tid < 128) {
            cp16(&SB[st][0][br_][bc_], Bhi + (size_t)(bn + br_) * CIN + k0 + bc_);
            cp16(&SB[st][1][br_][bc_], Blo + (size_t)(bn + br_) * CIN + k0 + bc_);
        }
    };

    issue(0, 0); cp_commit();
    issue(1, 1); cp_commit();
    cp_wait<1>();
    __syncthreads();

    for (int t = 0; t < NTILE; t++) {
        const int st = t & 1;
        // B fragments via ldmatrix: each x4 covers 2 n-tiles
        unsigned bh[NNT][2], bl[NNT][2];
#pragma unroll
        for (int p = 0; p < NNT / 2; p++) {
            const __nv_bfloat16* ph = &SB[st][0][nw + 16 * p + brow][bcol];
            const __nv_bfloat16* pl = &SB[st][1][nw + 16 * p + brow][bcol];
            ldmx4(bh[2 * p][0], bh[2 * p][1], bh[2 * p + 1][0], bh[2 * p + 1][1], ph);
            ldmx4(bl[2 * p][0], bl[2 * p][1], bl[2 * p + 1][0], bl[2 * p + 1][1], pl);
        }
#pragma unroll
        for (int mt = 0; mt < 4; mt++) {
            const __nv_bfloat16* pah = &SA[st][0][mw + 16 * mt + arow][acol];
            const __nv_bfloat16* pal = &SA[st][1][mw + 16 * mt + arow][acol];
            unsigned ah0, ah1, ah2, ah3, al0, al1, al2, al3;
            ldmx4(ah0, ah1, ah2, ah3, pah);
            ldmx4(al0, al1, al2, al3, pal);
#pragma unroll
            for (int nt = 0; nt < NNT; nt++) {
                float* d = acc[mt][nt];
                mma16816(d[0], d[1], d[2], d[3], ah0, ah1, ah2, ah3, bh[nt][0], bh[nt][1]);
                mma16816(d[0], d[1], d[2], d[3], ah0, ah1, ah2, ah3, bl[nt][0], bl[nt][1]);
                mma16816(d[0], d[1], d[2], d[3], al0, al1, al2, al3, bh[nt][0], bh[nt][1]);
            }
        }
        __syncthreads();
        if (t + 2 < NTILE) {
            issue(t + 2, st); cp_commit();
            cp_wait<1>();
        } else {
            cp_wait<0>();
        }
        __syncthreads();
    }

#pragma unroll
    for (int mt = 0; mt < 4; mt++) {
#pragma unroll
        for (int nt = 0; nt < NNT; nt++) {
            int m0 = bm + mw + 16 * mt + g;
            int n0 = bn + nw + 8 * nt + 2 * t4;
            float b0 = bias[n0], b1 = bias[n0 + 1];
            float* d = acc[mt][nt];
            float v0 = d[0] + b0, v1 = d[1] + b1;
            float v2 = d[2] + b0, v3 = d[3] + b1;
            if (EPI == 0) {
                int sel = n0 >> 8;
                int hh = (n0 >> 5) & 7;
                int dd = n0 & 31;
                size_t i0 = ((size_t)hh * S_ + m0) * DH + dd;
                size_t i1 = i0 + 8 * DH;
                if (sel == 0) {
                    *(float2*)&g_q[i0] = make_float2(v0, v1);
                    *(float2*)&g_q[i1] = make_float2(v2, v3);
                } else if (sel == 1) {
                    *(unsigned*)&g_khi[i0] = pack2bf(v0, v1);
                    *(unsigned*)&g_klo[i0] = pack2bf(bf_res(v0), bf_res(v1));
                    *(unsigned*)&g_khi[i1] = pack2bf(v2, v3);
                    *(unsigned*)&g_klo[i1] = pack2bf(bf_res(v2), bf_res(v3));
                } else {
                    *(unsigned*)&g_vhi[i0] = pack2bf(v0, v1);
                    *(unsigned*)&g_vlo[i0] = pack2bf(bf_res(v0), bf_res(v1));
                    *(unsigned*)&g_vhi[i1] = pack2bf(v2, v3);
                    *(unsigned*)&g_vlo[i1] = pack2bf(bf_res(v2), bf_res(v3));
                }
            } else {
                Cout[(size_t)n0 * S_ + m0]           = v0;
                Cout[(size_t)(n0 + 1) * S_ + m0]     = v1;
                Cout[(size_t)n0 * S_ + m0 + 8]       = v2;
                Cout[(size_t)(n0 + 1) * S_ + m0 + 8] = v3;
            }
        }
    }
}

// ---------------------------------------------------------------------------
// MMA neighborhood attention (unchanged from round 5).
// ---------------------------------------------------------------------------
#define TQX    16
#define TQY    8
#define WINX   22
#define NPOS   308
#define PQK    40                    // row pitch (bf16): 32 + 8 pad
#define SK_ELE (NPOS * PQK)          // 12320 els per array
#define NATTEN_SMEM (4 * SK_ELE * 2) // 98560 B

__global__ __launch_bounds__(256, 2) void natten_mma()
{
    extern __shared__ __nv_bfloat16 sm[];
    __nv_bfloat16* skh = sm;
    __nv_bfloat16* skl = sm + SK_ELE;
    __nv_bfloat16* svh = sm + 2 * SK_ELE;
    __nv_bfloat16* svl = sm + 3 * SK_ELE;

    const int h = blockIdx.z;
    const int qx0 = blockIdx.x * TQX, qy0 = blockIdx.y * TQY;
    const int wx0 = min(max(qx0 - 3, 0), W_ - WINX);
    const int wy0 = min(max(qy0 - 3, 0), H_ - 14);
    const int tid = threadIdx.x;
    const int lane = tid & 31, wid = tid >> 5;
    const int g = lane >> 2, t4 = lane & 3;
    const int lrow = lane & 7, lmat = lane >> 3;
    const float scale = 0.17677669529663687f;  // 1/sqrt(32)

    const size_t hb = (size_t)h * S_ * DH;

    // ---- stage K then V via cp.async (2 groups) ----
    {
        const __nv_bfloat16* Kh = g_khi + hb;
        const __nv_bfloat16* Kl = g_klo + hb;
        for (int c = tid; c < NPOS * 4; c += 256) {
            int p = c >> 2, off = (c & 3) * 8;
            int gy = wy0 + p / WINX, gx = wx0 + p % WINX;
            size_t gi = (size_t)(gy * W_ + gx) * DH + off;
            cp16(&skh[p * PQK + off], Kh + gi);
            cp16(&skl[p * PQK + off], Kl + gi);
        }
        cp_commit();
        const __nv_bfloat16* Vh = g_vhi + hb;
        const __nv_bfloat16* Vl = g_vlo + hb;
        for (int c = tid; c < NPOS * 4; c += 256) {
            int p = c >> 2, off = (c & 3) * 8;
            int gy = wy0 + p / WINX, gx = wx0 + p % WINX;
            size_t gi = (size_t)(gy * W_ + gx) * DH + off;
            cp16(&svh[p * PQK + off], Vh + gi);
            cp16(&svl[p * PQK + off], Vl + gi);
        }
        cp_commit();
    }

    // warp query subtile origin
    const int wxq = (wid & 1) * 8;
    const int wyq = (wid >> 1) * 2;
    const int qxg = qx0 + wxq + g;
    const int qyg0 = qy0 + wyq, qyg1 = qyg0 + 1;

    // warp window origin inside the block window
    const int cxs = min(max(qx0 + wxq, 3), W_ - 4);
    const int cys = min(max(qyg0, 3), H_ - 4);
    const int bx0 = min((cxs - 3 - wx0) & ~1, 6);
    const int by0 = min(cys - 3 - wy0, 6);

    // per-thread valid ranges (mask)
    const int cx = min(max(qxg, 3), W_ - 4);
    const int cy0 = min(max(qyg0, 3), H_ - 4);
    const int cy1 = min(max(qyg1, 3), H_ - 4);
    const int vx  = cx - 3 - wx0 - bx0;
    const int vy0 = cy0 - 3 - wy0 - by0;
    const int vy1 = cy1 - 3 - wy0 - by0;

    // ---- Q fragments from gmem fp32 (overlaps cp.async) ----
    const float* Qb = g_q + hb;
    unsigned qa_h[2][4], qa_l[2][4];
    {
        const size_t s0 = (size_t)(qyg0 * W_ + qxg) * DH;
        const size_t s1 = (size_t)(qyg1 * W_ + qxg) * DH;
#pragma unroll
        for (int kc = 0; kc < 2; kc++) {
            float2 u0 = *(const float2*)&Qb[s0 + kc * 16 + 2 * t4];
            float2 u1 = *(const float2*)&Qb[s1 + kc * 16 + 2 * t4];
            float2 w0 = *(const float2*)&Qb[s0 + kc * 16 + 8 + 2 * t4];
            float2 w1 = *(const float2*)&Qb[s1 + kc * 16 + 8 + 2 * t4];
            u0.x *= scale; u0.y *= scale; u1.x *= scale; u1.y *= scale;
            w0.x *= scale; w0.y *= scale; w1.x *= scale; w1.y *= scale;
            qa_h[kc][0] = pack2bf(u0.x, u0.y);
            qa_h[kc][1] = pack2bf(u1.x, u1.y);
            qa_h[kc][2] = pack2bf(w0.x, w0.y);
            qa_h[kc][3] = pack2bf(w1.x, w1.y);
            qa_l[kc][0] = pack2bf(bf_res(u0.x), bf_res(u0.y));
            qa_l[kc][1] = pack2bf(bf_res(u1.x), bf_res(u1.y));
            qa_l[kc][2] = pack2bf(bf_res(w0.x), bf_res(w0.y));
            qa_l[kc][3] = pack2bf(bf_res(w1.x), bf_res(w1.y));
        }
    }

    cp_wait<1>();     // K staged (V may still be in flight)
    __syncthreads();

    // ---- QK MMA: 16 n-tiles of 8 over the warp's 8x16 window ----
    const int kcol = (lmat & 1) * 8 + (lmat >> 1) * 16;   // ldmatrix col for K
    float acc[16][4];
#pragma unroll
    for (int nt = 0; nt < 16; nt++)
#pragma unroll
        for (int e = 0; e < 4; e++) acc[nt][e] = 0.f;

#pragma unroll
    for (int nt = 0; nt < 16; nt++) {
        const int pos0 = (by0 + (nt >> 1)) * WINX + bx0 + (nt & 1) * 8;
        unsigned bh0, bh1, bh2, bh3, bl0, bl1, bl2, bl3;
        ldmx4(bh0, bh1, bh2, bh3, &skh[(pos0 + lrow) * PQK + kcol]);
        ldmx4(bl0, bl1, bl2, bl3, &skl[(pos0 + lrow) * PQK + kcol]);
        float* d = acc[nt];
        mma16816(d[0], d[1], d[2], d[3], qa_h[0][0], qa_h[0][1], qa_h[0][2], qa_h[0][3], bh0, bh1);
        mma16816(d[0], d[1], d[2], d[3], qa_h[1][0], qa_h[1][1], qa_h[1][2], qa_h[1][3], bh2, bh3);
        mma16816(d[0], d[1], d[2], d[3], qa_h[0][0], qa_h[0][1], qa_h[0][2], qa_h[0][3], bl0, bl1);
        mma16816(d[0], d[1], d[2], d[3], qa_h[1][0], qa_h[1][1], qa_h[1][2], qa_h[1][3], bl2, bl3);
        mma16816(d[0], d[1], d[2], d[3], qa_l[0][0], qa_l[0][1], qa_l[0][2], qa_l[0][3], bh0, bh1);
        mma16816(d[0], d[1], d[2], d[3], qa_l[1][0], qa_l[1][1], qa_l[1][2], qa_l[1][3], bh2, bh3);
    }

    // ---- masked softmax (registers only) ----
    float mx0 = -1e30f, mx1 = -1e30f;
#pragma unroll
    for (int nt = 0; nt < 16; nt++) {
        const int jy = nt >> 1;
        const int jxb = (nt & 1) * 8 + 2 * t4;
#pragma unroll
        for (int e = 0; e < 2; e++) {
            const int jx = jxb + e;
            bool okx = (unsigned)(jx - vx) < 7u;
            bool ok0 = okx && ((unsigned)(jy - vy0) < 7u);
            bool ok1 = okx && ((unsigned)(jy - vy1) < 7u);
            acc[nt][e]     = ok0 ? acc[nt][e]     : -1e30f;
            acc[nt][2 + e] = ok1 ? acc[nt][2 + e] : -1e30f;
            mx0 = fmaxf(mx0, acc[nt][e]);
            mx1 = fmaxf(mx1, acc[nt][2 + e]);
        }
    }
    mx0 = fmaxf(mx0, __shfl_xor_sync(0xffffffffu, mx0, 1));
    mx0 = fmaxf(mx0, __shfl_xor_sync(0xffffffffu, mx0, 2));
    mx1 = fmaxf(mx1, __shfl_xor_sync(0xffffffffu, mx1, 1));
    mx1 = fmaxf(mx1, __shfl_xor_sync(0xffffffffu, mx1, 2));

    float sum0 = 0.f, sum1 = 0.f;
#pragma unroll
    for (int nt = 0; nt < 16; nt++) {
#pragma unroll
        for (int e = 0; e < 2; e++) {
            float p0 = __expf(acc[nt][e] - mx0);
            float p1 = __expf(acc[nt][2 + e] - mx1);
            acc[nt][e] = p0; acc[nt][2 + e] = p1;
            sum0 += p0; sum1 += p1;
        }
    }
    sum0 += __shfl_xor_sync(0xffffffffu, sum0, 1);
    sum0 += __shfl_xor_sync(0xffffffffu, sum0, 2);
    sum1 += __shfl_xor_sync(0xffffffffu, sum1, 1);
    sum1 += __shfl_xor_sync(0xffffffffu, sum1, 2);
    const float inv0 = 1.0f / sum0, inv1 = 1.0f / sum1;

    // ---- convert P in place to packed bf16 hi/lo A-fragments ----
#pragma unroll
    for (int nt = 0; nt < 16; nt++) {
        float p00 = acc[nt][0], p01 = acc[nt][1];
        float p10 = acc[nt][2], p11 = acc[nt][3];
        unsigned hh0 = pack2bf(p00, p01);
        unsigned hh1 = pack2bf(p10, p11);
        unsigned ll0 = pack2bf(bf_res(p00), bf_res(p01));
        unsigned ll1 = pack2bf(bf_res(p10), bf_res(p11));
        acc[nt][0] = __uint_as_float(hh0);
        acc[nt][1] = __uint_as_float(hh1);
        acc[nt][2] = __uint_as_float(ll0);
        acc[nt][3] = __uint_as_float(ll1);
    }

    cp_wait<0>();     // V staged
    __syncthreads();

    // ---- PV MMA: 8 k-tiles of 16 positions, n = dh 32 via ldmatrix.trans ----
    float o[4][4];
#pragma unroll
    for (int vt = 0; vt < 4; vt++)
#pragma unroll
        for (int e = 0; e < 4; e++) o[vt][e] = 0.f;

    const int vrow = (lmat & 1) * 8 + lrow;     // ldmatrix row offset for V
    const int vmat = (lmat >> 1) * 8;           // col sub-offset
#pragma unroll
    for (int kt = 0; kt < 8; kt++) {
        const int prow = (by0 + kt) * WINX + bx0;
        unsigned ah0 = __float_as_uint(acc[2 * kt][0]);
        unsigned ah1 = __float_as_uint(acc[2 * kt][1]);
        unsigned ah2 = __float_as_uint(acc[2 * kt + 1][0]);
        unsigned ah3 = __float_as_uint(acc[2 * kt + 1][1]);
        unsigned al0 = __float_as_uint(acc[2 * kt][2]);
        unsigned al1 = __float_as_uint(acc[2 * kt][3]);
        unsigned al2 = __float_as_uint(acc[2 * kt + 1][2]);
        unsigned al3 = __float_as_uint(acc[2 * kt + 1][3]);
#pragma unroll
        for (int half = 0; half < 2; half++) {
            unsigned bh0, bh1, bh2, bh3, bl0, bl1, bl2, bl3;
            const int col = half * 16 + vmat;
            ldmx4t(bh0, bh1, bh2, bh3, &svh[(prow + vrow) * PQK + col]);
            ldmx4t(bl0, bl1, bl2, bl3, &svl[(prow + vrow) * PQK + col]);
            float* d0 = o[2 * half];
            float* d1 = o[2 * half + 1];
            mma16816(d0[0], d0[1], d0[2], d0[3], ah0, ah1, ah2, ah3, bh0, bh1);
            mma16816(d0[0], d0[1], d0[2], d0[3], ah0, ah1, ah2, ah3, bl0, bl1);
            mma16816(d0[0], d0[1], d0[2], d0[3], al0, al1, al2, al3, bh0, bh1);
            mma16816(d1[0], d1[1], d1[2], d1[3], ah0, ah1, ah2, ah3, bh2, bh3);
            mma16816(d1[0], d1[1], d1[2], d1[3], ah0, ah1, ah2, ah3, bl2, bl3);
            mma16816(d1[0], d1[1], d1[2], d1[3], al0, al1, al2, al3, bh2, bh3);
        }
    }

    // ---- epilogue: normalize, split, store [s][h*32+d] ----
    {
        size_t s0 = (size_t)(qyg0 * W_ + qxg) * CIN + h * DH;
        size_t s1 = (size_t)(qyg1 * W_ + qxg) * CIN + h * DH;
#pragma unroll
        for (int vt = 0; vt < 4; vt++) {
            int c = vt * 8 + 2 * t4;
            float f00 = o[vt][0] * inv0, f01 = o[vt][1] * inv0;
            float f10 = o[vt][2] * inv1, f11 = o[vt][3] * inv1;
            *(unsigned*)&g_ahi[s0 + c] = pack2bf(f00, f01);
            *(unsigned*)&g_alo[s0 + c] = pack2bf(bf_res(f00), bf_res(f01));
            *(unsigned*)&g_ahi[s1 + c] = pack2bf(f10, f11);
            *(unsigned*)&g_alo[s1 + c] = pack2bf(bf_res(f10), bf_res(f11));
        }
    }
}

// ---------------------------------------------------------------------------
extern "C" void kernel_launch(void* const* d_in, const int* in_sizes, int n_in,
                              void* d_out, int out_size)
{
    const float* x     = (const float*)d_in[0];   // [256][9216]
    const float* w_qkv = (const float*)d_in[1];   // [768][256]
    const float* b_qkv = (const float*)d_in[2];   // [768]
    const float* w_out = (const float*)d_in[3];   // [256][256]
    const float* b_out = (const float*)d_in[4];   // [256]
    float* out = (float*)d_out;                   // [256][9216]

    cudaFuncSetAttribute(natten_mma,
                         cudaFuncAttributeMaxDynamicSharedMemorySize, NATTEN_SMEM);

    split_all_kernel<<<NBX + 64, 256>>>(x, w_qkv, w_out);

    __nv_bfloat16 *xhi, *xlo, *wqhi, *wqlo, *wohi, *wolo, *ahi, *alo;
    cudaGetSymbolAddress((void**)&xhi,  g_xhi);
    cudaGetSymbolAddress((void**)&xlo,  g_xlo);
    cudaGetSymbolAddress((void**)&wqhi, g_wqhi);
    cudaGetSymbolAddress((void**)&wqlo, g_wqlo);
    cudaGetSymbolAddress((void**)&wohi, g_wohi);
    cudaGetSymbolAddress((void**)&wolo, g_wolo);
    cudaGetSymbolAddress((void**)&ahi,  g_ahi);
    cudaGetSymbolAddress((void**)&alo,  g_alo);

    gemm_bf16x3<128, 0><<<dim3(S_ / 128, 768 / 128), 256>>>(
        xhi, xlo, wqhi, wqlo, b_qkv, nullptr);

    natten_mma<<<dim3(W_ / TQX, H_ / TQY, NH), 256, NATTEN_SMEM>>>();

    gemm_bf16x3<64, 1><<<dim3(S_ / 128, CIN / 64), 256>>>(
        ahi, alo, wohi, wolo, b_out, out);
}

// round 7
// speedup vs baseline: 2.0907x; 1.0481x over previous
#include <cuda_runtime.h>
#include <cuda_bf16.h>
#include <cstdint>

#define H_   96
#define W_   96
#define S_   9216
#define CIN  256
#define NH   8
#define DH   32

// attention operands produced by qkv GEMM
__device__ float         g_q[NH * S_ * DH];            // fp32 Q
__device__ __nv_bfloat16 g_khi[NH * S_ * DH];          // K split
__device__ __nv_bfloat16 g_klo[NH * S_ * DH];
__device__ __nv_bfloat16 g_vhi[NH * S_ * DH];          // V split
__device__ __nv_bfloat16 g_vlo[NH * S_ * DH];
// bf16 split GEMM inputs
__device__ __nv_bfloat16 g_xhi[S_ * CIN];   // x transposed: [s][c]
__device__ __nv_bfloat16 g_xlo[S_ * CIN];
__device__ __nv_bfloat16 g_wqhi[768 * CIN];
__device__ __nv_bfloat16 g_wqlo[768 * CIN];
__device__ __nv_bfloat16 g_wohi[CIN * CIN];
__device__ __nv_bfloat16 g_wolo[CIN * CIN];
__device__ __nv_bfloat16 g_ahi[S_ * CIN];   // attention out split: [s][c]
__device__ __nv_bfloat16 g_alo[S_ * CIN];

// ---------------------------------------------------------------------------
// helpers
// ---------------------------------------------------------------------------
__device__ __forceinline__ void cp16(void* sdst, const void* gsrc) {
    unsigned d = (unsigned)__cvta_generic_to_shared(sdst);
    asm volatile("cp.async.cg.shared.global [%0], [%1], 16;" :: "r"(d), "l"(gsrc));
}
__device__ __forceinline__ void cp_commit() {
    asm volatile("cp.async.commit_group;");
}
template<int N> __device__ __forceinline__ void cp_wait() {
    asm volatile("cp.async.wait_group %0;" :: "n"(N));
}
__device__ __forceinline__ void mma16816(float& d0, float& d1, float& d2, float& d3,
                                         unsigned a0, unsigned a1, unsigned a2, unsigned a3,
                                         unsigned b0, unsigned b1) {
    asm volatile(
        "mma.sync.aligned.m16n8k16.row.col.f32.bf16.bf16.f32 "
        "{%0,%1,%2,%3},{%4,%5,%6,%7},{%8,%9},{%0,%1,%2,%3};"
        : "+f"(d0), "+f"(d1), "+f"(d2), "+f"(d3)
        : "r"(a0), "r"(a1), "r"(a2), "r"(a3), "r"(b0), "r"(b1));
}
__device__ __forceinline__ void ldmx4(unsigned& r0, unsigned& r1, unsigned& r2, unsigned& r3,
                                      const __nv_bfloat16* p) {
    unsigned a = (unsigned)__cvta_generic_to_shared(p);
    asm volatile("ldmatrix.sync.aligned.m8n8.x4.shared.b16 {%0,%1,%2,%3}, [%4];"
                 : "=r"(r0), "=r"(r1), "=r"(r2), "=r"(r3) : "r"(a));
}
__device__ __forceinline__ void ldmx4t(unsigned& r0, unsigned& r1, unsigned& r2, unsigned& r3,
                                       const __nv_bfloat16* p) {
    unsigned a = (unsigned)__cvta_generic_to_shared(p);
    asm volatile("ldmatrix.sync.aligned.m8n8.x4.trans.shared.b16 {%0,%1,%2,%3}, [%4];"
                 : "=r"(r0), "=r"(r1), "=r"(r2), "=r"(r3) : "r"(a));
}
__device__ __forceinline__ void split_bf16(float v, __nv_bfloat16& hi, __nv_bfloat16& lo) {
    hi = __float2bfloat16_rn(v);
    lo = __float2bfloat16_rn(v - __bfloat162float(hi));
}
__device__ __forceinline__ float bf_res(float v) {
    return v - __bfloat162float(__float2bfloat16_rn(v));
}
__device__ __forceinline__ unsigned pack2bf(float x, float y) {
    __nv_bfloat162 t = __floats2bfloat162_rn(x, y);   // .x = low half
    return *reinterpret_cast<unsigned*>(&t);
}

// ---------------------------------------------------------------------------
// prep (merged): blocks [0, 2304): transpose+split x [C][S] -> xhi/xlo [S][C]
//                blocks [2304, 2368): split both weight matrices
// ---------------------------------------------------------------------------
#define NBX 2304   // (S_/32) * (CIN/32)

__global__ __launch_bounds__(256) void split_all_kernel(
    const float* __restrict__ x, const float* __restrict__ wq,
    const float* __restrict__ wo)
{
    __shared__ float tile[32][33];
    if (blockIdx.x < NBX) {
        const int m0 = (blockIdx.x % (S_ / 32)) * 32;   // s
        const int k0 = (blockIdx.x / (S_ / 32)) * 32;   // c
        const int tx = threadIdx.x & 31, ty = threadIdx.x >> 5;
#pragma unroll
        for (int i = 0; i < 4; i++)
            tile[ty + 8 * i][tx] = x[(k0 + ty + 8 * i) * S_ + m0 + tx];
        __syncthreads();
#pragma unroll
        for (int i = 0; i < 4; i++) {
            int row = ty + 8 * i;
            float v = tile[tx][row];
            __nv_bfloat16 hi, lo;
            split_bf16(v, hi, lo);
            g_xhi[(m0 + row) * CIN + k0 + tx] = hi;
            g_xlo[(m0 + row) * CIN + k0 + tx] = lo;
        }
    } else {
        const int NQ = 768 * CIN;
        const int NO = CIN * CIN;
        const int bid = blockIdx.x - NBX;
        for (int i = bid * 256 + threadIdx.x; i < NQ + NO; i += 64 * 256) {
            __nv_bfloat16 hi, lo;
            if (i < NQ) {
                split_bf16(wq[i], hi, lo);
                g_wqhi[i] = hi; g_wqlo[i] = lo;
            } else {
                int j = i - NQ;
                split_bf16(wo[j], hi, lo);
                g_wohi[j] = hi; g_wolo[j] = lo;
            }
        }
    }
}

// ---------------------------------------------------------------------------
// bf16x3 GEMM, 4-stage cp.async multistage, ONE __syncthreads per k-iter.
// C[m][n] = sum_k A[m][k]*B[n][k], M tile 128, N tile BN, K=256.
// EPI 0: write q fp32 / k,v bf16-split (BN=128). EPI 1: NCHW fp32 (BN=64).
// ---------------------------------------------------------------------------
#define PITCH 24
#define NTILE 16
#define NS    4

template<int BN, int EPI>
__global__ __launch_bounds__(256, 2) void gemm_bf16x3(
    const __nv_bfloat16* __restrict__ Ahi, const __nv_bfloat16* __restrict__ Alo,
    const __nv_bfloat16* __restrict__ Bhi, const __nv_bfloat16* __restrict__ Blo,
    const float* __restrict__ bias, float* __restrict__ Cout)
{
    constexpr int NNT = BN / 32;         // n-tiles (of 8) per warp
    __shared__ __nv_bfloat16 SA[NS][2][128][PITCH];
    __shared__ __nv_bfloat16 SB[NS][2][BN][PITCH];

    const int bm = blockIdx.x * 128;
    const int bn = blockIdx.y * BN;
    const int tid = threadIdx.x;
    const int lane = tid & 31, wid = tid >> 5;
    const int g = lane >> 2, t4 = lane & 3;
    const int mw = (wid & 1) * 64;
    const int nw = (wid >> 1) * (BN / 4);

    // ldmatrix per-lane offsets
    const int arow = (lane & 7) + ((lane >> 3) & 1) * 8;
    const int acol = (lane >> 4) * 8;
    const int brow = (lane & 7) + (lane >> 4) * 8;
    const int bcol = ((lane >> 3) & 1) * 8;

    // loaders
    const int lr = tid >> 1;
    const int lc = (tid & 1) * 8;

    float acc[4][NNT][4];
#pragma unroll
    for (int a = 0; a < 4; a++)
#pragma unroll
        for (int b = 0; b < NNT; b++)
#pragma unroll
            for (int c = 0; c < 4; c++) acc[a][b][c] = 0.f;

    auto issue = [&](int t) {
        int st = t & (NS - 1);
        int k0 = t * 16;
        cp16(&SA[st][0][lr][lc], Ahi + (size_t)(bm + lr) * CIN + k0 + lc);
        cp16(&SA[st][1][lr][lc], Alo + (size_t)(bm + lr) * CIN + k0 + lc);
        if (BN == 128 || tid < 128) {
            cp16(&SB[st][0][lr][lc], Bhi + (size_t)(bn + lr) * CIN + k0 + lc);
            cp16(&SB[st][1][lr][lc], Blo + (size_t)(bn + lr) * CIN + k0 + lc);
        }
    };

    // prologue: stages 0..NS-2
#pragma unroll
    for (int p = 0; p < NS - 1; p++) { issue(p); cp_commit(); }

    for (int t = 0; t < NTILE; t++) {
        const int st = t & (NS - 1);
        cp_wait<NS - 2>();
        __syncthreads();                 // stage t ready; stage t-1 free to overwrite
        if (t + NS - 1 < NTILE) issue(t + NS - 1);
        cp_commit();                     // empty commits keep group accounting exact

        unsigned bh[NNT][2], bl[NNT][2];
#pragma unroll
        for (int p = 0; p < NNT / 2; p++) {
            const __nv_bfloat16* ph = &SB[st][0][nw + 16 * p + brow][bcol];
            const __nv_bfloat16* pl = &SB[st][1][nw + 16 * p + brow][bcol];
            ldmx4(bh[2 * p][0], bh[2 * p][1], bh[2 * p + 1][0], bh[2 * p + 1][1], ph);
            ldmx4(bl[2 * p][0], bl[2 * p][1], bl[2 * p + 1][0], bl[2 * p + 1][1], pl);
        }
#pragma unroll
        for (int mt = 0; mt < 4; mt++) {
            const __nv_bfloat16* pah = &SA[st][0][mw + 16 * mt + arow][acol];
            const __nv_bfloat16* pal = &SA[st][1][mw + 16 * mt + arow][acol];
            unsigned ah0, ah1, ah2, ah3, al0, al1, al2, al3;
            ldmx4(ah0, ah1, ah2, ah3, pah);
            ldmx4(al0, al1, al2, al3, pal);
#pragma unroll
            for (int nt = 0; nt < NNT; nt++) {
                float* d = acc[mt][nt];
                mma16816(d[0], d[1], d[2], d[3], ah0, ah1, ah2, ah3, bh[nt][0], bh[nt][1]);
                mma16816(d[0], d[1], d[2], d[3], ah0, ah1, ah2, ah3, bl[nt][0], bl[nt][1]);
                mma16816(d[0], d[1], d[2], d[3], al0, al1, al2, al3, bh[nt][0], bh[nt][1]);
            }
        }
    }

#pragma unroll
    for (int mt = 0; mt < 4; mt++) {
#pragma unroll
        for (int nt = 0; nt < NNT; nt++) {
            int m0 = bm + mw + 16 * mt + g;
            int n0 = bn + nw + 8 * nt + 2 * t4;
            float b0 = bias[n0], b1 = bias[n0 + 1];
            float* d = acc[mt][nt];
            float v0 = d[0] + b0, v1 = d[1] + b1;
            float v2 = d[2] + b0, v3 = d[3] + b1;
            if (EPI == 0) {
                int sel = n0 >> 8;
                int hh = (n0 >> 5) & 7;
                int dd = n0 & 31;
                size_t i0 = ((size_t)hh * S_ + m0) * DH + dd;
                size_t i1 = i0 + 8 * DH;
                if (sel == 0) {
                    *(float2*)&g_q[i0] = make_float2(v0, v1);
                    *(float2*)&g_q[i1] = make_float2(v2, v3);
                } else if (sel == 1) {
                    *(unsigned*)&g_khi[i0] = pack2bf(v0, v1);
                    *(unsigned*)&g_klo[i0] = pack2bf(bf_res(v0), bf_res(v1));
                    *(unsigned*)&g_khi[i1] = pack2bf(v2, v3);
                    *(unsigned*)&g_klo[i1] = pack2bf(bf_res(v2), bf_res(v3));
                } else {
                    *(unsigned*)&g_vhi[i0] = pack2bf(v0, v1);
                    *(unsigned*)&g_vlo[i0] = pack2bf(bf_res(v0), bf_res(v1));
                    *(unsigned*)&g_vhi[i1] = pack2bf(v2, v3);
                    *(unsigned*)&g_vlo[i1] = pack2bf(bf_res(v2), bf_res(v3));
                }
            } else {
                Cout[(size_t)n0 * S_ + m0]           = v0;
                Cout[(size_t)(n0 + 1) * S_ + m0]     = v1;
                Cout[(size_t)n0 * S_ + m0 + 8]       = v2;
                Cout[(size_t)(n0 + 1) * S_ + m0 + 8] = v3;
            }
        }
    }
}

// ---------------------------------------------------------------------------
// MMA neighborhood attention (unchanged from round 5/6).
// ---------------------------------------------------------------------------
#define TQX    16
#define TQY    8
#define WINX   22
#define NPOS   308
#define PQK    40                    // row pitch (bf16): 32 + 8 pad
#define SK_ELE (NPOS * PQK)          // 12320 els per array
#define NATTEN_SMEM (4 * SK_ELE * 2) // 98560 B

__global__ __launch_bounds__(256, 2) void natten_mma()
{
    extern __shared__ __nv_bfloat16 sm[];
    __nv_bfloat16* skh = sm;
    __nv_bfloat16* skl = sm + SK_ELE;
    __nv_bfloat16* svh = sm + 2 * SK_ELE;
    __nv_bfloat16* svl = sm + 3 * SK_ELE;

    const int h = blockIdx.z;
    const int qx0 = blockIdx.x * TQX, qy0 = blockIdx.y * TQY;
    const int wx0 = min(max(qx0 - 3, 0), W_ - WINX);
    const int wy0 = min(max(qy0 - 3, 0), H_ - 14);
    const int tid = threadIdx.x;
    const int lane = tid & 31, wid = tid >> 5;
    const int g = lane >> 2, t4 = lane & 3;
    const int lrow = lane & 7, lmat = lane >> 3;
    const float scale = 0.17677669529663687f;  // 1/sqrt(32)

    const size_t hb = (size_t)h * S_ * DH;

    // ---- stage K then V via cp.async (2 groups) ----
    {
        const __nv_bfloat16* Kh = g_khi + hb;
        const __nv_bfloat16* Kl = g_klo + hb;
        for (int c = tid; c < NPOS * 4; c += 256) {
            int p = c >> 2, off = (c & 3) * 8;
            int gy = wy0 + p / WINX, gx = wx0 + p % WINX;
            size_t gi = (size_t)(gy * W_ + gx) * DH + off;
            cp16(&skh[p * PQK + off], Kh + gi);
            cp16(&skl[p * PQK + off], Kl + gi);
        }
        cp_commit();
        const __nv_bfloat16* Vh = g_vhi + hb;
        const __nv_bfloat16* Vl = g_vlo + hb;
        for (int c = tid; c < NPOS * 4; c += 256) {
            int p = c >> 2, off = (c & 3) * 8;
            int gy = wy0 + p / WINX, gx = wx0 + p % WINX;
            size_t gi = (size_t)(gy * W_ + gx) * DH + off;
            cp16(&svh[p * PQK + off], Vh + gi);
            cp16(&svl[p * PQK + off], Vl + gi);
        }
        cp_commit();
    }

    // warp query subtile origin
    const int wxq = (wid & 1) * 8;
    const int wyq = (wid >> 1) * 2;
    const int qxg = qx0 + wxq + g;
    const int qyg0 = qy0 + wyq, qyg1 = qyg0 + 1;

    // warp window origin inside the block window
    const int cxs = min(max(qx0 + wxq, 3), W_ - 4);
    const int cys = min(max(qyg0, 3), H_ - 4);
    const int bx0 = min((cxs - 3 - wx0) & ~1, 6);
    const int by0 = min(cys - 3 - wy0, 6);

    // per-thread valid ranges (mask)
    const int cx = min(max(qxg, 3), W_ - 4);
    const int cy0 = min(max(qyg0, 3), H_ - 4);
    const int cy1 = min(max(qyg1, 3), H_ - 4);
    const int vx  = cx - 3 - wx0 - bx0;
    const int vy0 = cy0 - 3 - wy0 - by0;
    const int vy1 = cy1 - 3 - wy0 - by0;

    // ---- Q fragments from gmem fp32 (overlaps cp.async) ----
    const float* Qb = g_q + hb;
    unsigned qa_h[2][4], qa_l[2][4];
    {
        const size_t s0 = (size_t)(qyg0 * W_ + qxg) * DH;
        const size_t s1 = (size_t)(qyg1 * W_ + qxg) * DH;
#pragma unroll
        for (int kc = 0; kc < 2; kc++) {
            float2 u0 = *(const float2*)&Qb[s0 + kc * 16 + 2 * t4];
            float2 u1 = *(const float2*)&Qb[s1 + kc * 16 + 2 * t4];
            float2 w0 = *(const float2*)&Qb[s0 + kc * 16 + 8 + 2 * t4];
            float2 w1 = *(const float2*)&Qb[s1 + kc * 16 + 8 + 2 * t4];
            u0.x *= scale; u0.y *= scale; u1.x *= scale; u1.y *= scale;
            w0.x *= scale; w0.y *= scale; w1.x *= scale; w1.y *= scale;
            qa_h[kc][0] = pack2bf(u0.x, u0.y);
            qa_h[kc][1] = pack2bf(u1.x, u1.y);
            qa_h[kc][2] = pack2bf(w0.x, w0.y);
            qa_h[kc][3] = pack2bf(w1.x, w1.y);
            qa_l[kc][0] = pack2bf(bf_res(u0.x), bf_res(u0.y));
            qa_l[kc][1] = pack2bf(bf_res(u1.x), bf_res(u1.y));
            qa_l[kc][2] = pack2bf(bf_res(w0.x), bf_res(w0.y));
            qa_l[kc][3] = pack2bf(bf_res(w1.x), bf_res(w1.y));
        }
    }

    cp_wait<1>();     // K staged (V may still be in flight)
    __syncthreads();

    // ---- QK MMA: 16 n-tiles of 8 over the warp's 8x16 window ----
    const int kcol = (lmat & 1) * 8 + (lmat >> 1) * 16;   // ldmatrix col for K
    float acc[16][4];
#pragma unroll
    for (int nt = 0; nt < 16; nt++)
#pragma unroll
        for (int e = 0; e < 4; e++) acc[nt][e] = 0.f;

#pragma unroll
    for (int nt = 0; nt < 16; nt++) {
        const int pos0 = (by0 + (nt >> 1)) * WINX + bx0 + (nt & 1) * 8;
        unsigned bh0, bh1, bh2, bh3, bl0, bl1, bl2, bl3;
        ldmx4(bh0, bh1, bh2, bh3, &skh[(pos0 + lrow) * PQK + kcol]);
        ldmx4(bl0, bl1, bl2, bl3, &skl[(pos0 + lrow) * PQK + kcol]);
        float* d = acc[nt];
        mma16816(d[0], d[1], d[2], d[3], qa_h[0][0], qa_h[0][1], qa_h[0][2], qa_h[0][3], bh0, bh1);
        mma16816(d[0], d[1], d[2], d[3], qa_h[1][0], qa_h[1][1], qa_h[1][2], qa_h[1][3], bh2, bh3);
        mma16816(d[0], d[1], d[2], d[3], qa_h[0][0], qa_h[0][1], qa_h[0][2], qa_h[0][3], bl0, bl1);
        mma16816(d[0], d[1], d[2], d[3], qa_h[1][0], qa_h[1][1], qa_h[1][2], qa_h[1][3], bl2, bl3);
        mma16816(d[0], d[1], d[2], d[3], qa_l[0][0], qa_l[0][1], qa_l[0][2], qa_l[0][3], bh0, bh1);
        mma16816(d[0], d[1], d[2], d[3], qa_l[1][0], qa_l[1][1], qa_l[1][2], qa_l[1][3], bh2, bh3);
    }

    // ---- masked softmax (registers only) ----
    float mx0 = -1e30f, mx1 = -1e30f;
#pragma unroll
    for (int nt = 0; nt < 16; nt++) {
        const int jy = nt >> 1;
        const int jxb = (nt & 1) * 8 + 2 * t4;
#pragma unroll
        for (int e = 0; e < 2; e++) {
            const int jx = jxb + e;
            bool okx = (unsigned)(jx - vx) < 7u;
            bool ok0 = okx && ((unsigned)(jy - vy0) < 7u);
            bool ok1 = okx && ((unsigned)(jy - vy1) < 7u);
            acc[nt][e]     = ok0 ? acc[nt][e]     : -1e30f;
            acc[nt][2 + e] = ok1 ? acc[nt][2 + e] : -1e30f;
            mx0 = fmaxf(mx0, acc[nt][e]);
            mx1 = fmaxf(mx1, acc[nt][2 + e]);
        }
    }
    mx0 = fmaxf(mx0, __shfl_xor_sync(0xffffffffu, mx0, 1));
    mx0 = fmaxf(mx0, __shfl_xor_sync(0xffffffffu, mx0, 2));
    mx1 = fmaxf(mx1, __shfl_xor_sync(0xffffffffu, mx1, 1));
    mx1 = fmaxf(mx1, __shfl_xor_sync(0xffffffffu, mx1, 2));

    float sum0 = 0.f, sum1 = 0.f;
#pragma unroll
    for (int nt = 0; nt < 16; nt++) {
#pragma unroll
        for (int e = 0; e < 2; e++) {
            float p0 = __expf(acc[nt][e] - mx0);
            float p1 = __expf(acc[nt][2 + e] - mx1);
            acc[nt][e] = p0; acc[nt][2 + e] = p1;
            sum0 += p0; sum1 += p1;
        }
    }
    sum0 += __shfl_xor_sync(0xffffffffu, sum0, 1);
    sum0 += __shfl_xor_sync(0xffffffffu, sum0, 2);
    sum1 += __shfl_xor_sync(0xffffffffu, sum1, 1);
    sum1 += __shfl_xor_sync(0xffffffffu, sum1, 2);
    const float inv0 = 1.0f / sum0, inv1 = 1.0f / sum1;

    // ---- convert P in place to packed bf16 hi/lo A-fragments ----
#pragma unroll
    for (int nt = 0; nt < 16; nt++) {
        float p00 = acc[nt][0], p01 = acc[nt][1];
        float p10 = acc[nt][2], p11 = acc[nt][3];
        unsigned hh0 = pack2bf(p00, p01);
        unsigned hh1 = pack2bf(p10, p11);
        unsigned ll0 = pack2bf(bf_res(p00), bf_res(p01));
        unsigned ll1 = pack2bf(bf_res(p10), bf_res(p11));
        acc[nt][0] = __uint_as_float(hh0);
        acc[nt][1] = __uint_as_float(hh1);
        acc[nt][2] = __uint_as_float(ll0);
        acc[nt][3] = __uint_as_float(ll1);
    }

    cp_wait<0>();     // V staged
    __syncthreads();

    // ---- PV MMA: 8 k-tiles of 16 positions, n = dh 32 via ldmatrix.trans ----
    float o[4][4];
#pragma unroll
    for (int vt = 0; vt < 4; vt++)
#pragma unroll
        for (int e = 0; e < 4; e++) o[vt][e] = 0.f;

    const int vrow = (lmat & 1) * 8 + lrow;     // ldmatrix row offset for V
    const int vmat = (lmat >> 1) * 8;           // col sub-offset
#pragma unroll
    for (int kt = 0; kt < 8; kt++) {
        const int prow = (by0 + kt) * WINX + bx0;
        unsigned ah0 = __float_as_uint(acc[2 * kt][0]);
        unsigned ah1 = __float_as_uint(acc[2 * kt][1]);
        unsigned ah2 = __float_as_uint(acc[2 * kt + 1][0]);
        unsigned ah3 = __float_as_uint(acc[2 * kt + 1][1]);
        unsigned al0 = __float_as_uint(acc[2 * kt][2]);
        unsigned al1 = __float_as_uint(acc[2 * kt][3]);
        unsigned al2 = __float_as_uint(acc[2 * kt + 1][2]);
        unsigned al3 = __float_as_uint(acc[2 * kt + 1][3]);
#pragma unroll
        for (int half = 0; half < 2; half++) {
            unsigned bh0, bh1, bh2, bh3, bl0, bl1, bl2, bl3;
            const int col = half * 16 + vmat;
            ldmx4t(bh0, bh1, bh2, bh3, &svh[(prow + vrow) * PQK + col]);
            ldmx4t(bl0, bl1, bl2, bl3, &svl[(prow + vrow) * PQK + col]);
            float* d0 = o[2 * half];
            float* d1 = o[2 * half + 1];
            mma16816(d0[0], d0[1], d0[2], d0[3], ah0, ah1, ah2, ah3, bh0, bh1);
            mma16816(d0[0], d0[1], d0[2], d0[3], ah0, ah1, ah2, ah3, bl0, bl1);
            mma16816(d0[0], d0[1], d0[2], d0[3], al0, al1, al2, al3, bh0, bh1);
            mma16816(d1[0], d1[1], d1[2], d1[3], ah0, ah1, ah2, ah3, bh2, bh3);
            mma16816(d1[0], d1[1], d1[2], d1[3], ah0, ah1, ah2, ah3, bl2, bl3);
            mma16816(d1[0], d1[1], d1[2], d1[3], al0, al1, al2, al3, bh2, bh3);
        }
    }

    // ---- epilogue: normalize, split, store [s][h*32+d] ----
    {
        size_t s0 = (size_t)(qyg0 * W_ + qxg) * CIN + h * DH;
        size_t s1 = (size_t)(qyg1 * W_ + qxg) * CIN + h * DH;
#pragma unroll
        for (int vt = 0; vt < 4; vt++) {
            int c = vt * 8 + 2 * t4;
            float f00 = o[vt][0] * inv0, f01 = o[vt][1] * inv0;
            float f10 = o[vt][2] * inv1, f11 = o[vt][3] * inv1;
            *(unsigned*)&g_ahi[s0 + c] = pack2bf(f00, f01);
            *(unsigned*)&g_alo[s0 + c] = pack2bf(bf_res(f00), bf_res(f01));
            *(unsigned*)&g_ahi[s1 + c] = pack2bf(f10, f11);
            *(unsigned*)&g_alo[s1 + c] = pack2bf(bf_res(f10), bf_res(f11));
        }
    }
}

// ---------------------------------------------------------------------------
extern "C" void kernel_launch(void* const* d_in, const int* in_sizes, int n_in,
                              void* d_out, int out_size)
{
    const float* x     = (const float*)d_in[0];   // [256][9216]
    const float* w_qkv = (const float*)d_in[1];   // [768][256]
    const float* b_qkv = (const float*)d_in[2];   // [768]
    const float* w_out = (const float*)d_in[3];   // [256][256]
    const float* b_out = (const float*)d_in[4];   // [256]
    float* out = (float*)d_out;                   // [256][9216]

    cudaFuncSetAttribute(natten_mma,
                         cudaFuncAttributeMaxDynamicSharedMemorySize, NATTEN_SMEM);

    split_all_kernel<<<NBX + 64, 256>>>(x, w_qkv, w_out);

    __nv_bfloat16 *xhi, *xlo, *wqhi, *wqlo, *wohi, *wolo, *ahi, *alo;
    cudaGetSymbolAddress((void**)&xhi,  g_xhi);
    cudaGetSymbolAddress((void**)&xlo,  g_xlo);
    cudaGetSymbolAddress((void**)&wqhi, g_wqhi);
    cudaGetSymbolAddress((void**)&wqlo, g_wqlo);
    cudaGetSymbolAddress((void**)&wohi, g_wohi);
    cudaGetSymbolAddress((void**)&wolo, g_wolo);
    cudaGetSymbolAddress((void**)&ahi,  g_ahi);
    cudaGetSymbolAddress((void**)&alo,  g_alo);

    gemm_bf16x3<128, 0><<<dim3(S_ / 128, 768 / 128), 256>>>(
        xhi, xlo, wqhi, wqlo, b_qkv, nullptr);

    natten_mma<<<dim3(W_ / TQX, H_ / TQY, NH), 256, NATTEN_SMEM>>>();

    gemm_bf16x3<64, 1><<<dim3(S_ / 128, CIN / 64), 256>>>(
        ahi, alo, wohi, wolo, b_out, out);
}